// round 1
// baseline (speedup 1.0000x reference)
#include <cuda_runtime.h>
#include <math.h>

// Problem dims (fixed)
#define BB 16
#define NN_SEQ 2048
#define MM 512
#define HH 512
#define BN_ROWS (BB * NN_SEQ)   // 32768

// GEMM tiling
#define TBM 128
#define TBN 128
#define TBK 16
#define TM 8
#define TN 8
#define NTHREADS 256

// Scratch (device globals; no runtime allocation allowed)
__device__ float g_q[BN_ROWS * HH];
__device__ float g_k[BN_ROWS * HH];
__device__ float g_v[BN_ROWS * HH];
__device__ float g_o[BN_ROWS * HH];
__device__ float g_hid[BN_ROWS * HH];
__device__ float g_att[(long long)BB * NN_SEQ * NN_SEQ];

// ---------------------------------------------------------------------------
// Generic fp32 SGEMM: C = A * B (or A * B^T) [+ bias] [relu]
// A: [Mrows, K] row-major.  B: NN -> [K, Ncols] row-major, NT -> [Ncols, K].
// All dims multiples of tile sizes (true for this problem), no bounds checks.
// blockIdx.z = batch index with given element strides.
// ---------------------------------------------------------------------------
template <bool TRANS_B, bool HAS_BIAS, bool RELU>
__global__ __launch_bounds__(NTHREADS, 2)
void sgemm_kernel(const float* __restrict__ A, const float* __restrict__ Bm,
                  const float* __restrict__ bias, float* __restrict__ C,
                  int Mrows, int Ncols, int K,
                  long long sA, long long sB, long long sC)
{
    const long long b = blockIdx.z;
    A  += b * sA;
    Bm += b * sB;
    C  += b * sC;

    __shared__ float As[TBK][TBM];
    __shared__ float Bs[TBK][TBN];

    const int tid = threadIdx.x;
    const int tx = tid & 15;   // 0..15  -> column group
    const int ty = tid >> 4;   // 0..15  -> row group

    const int m0 = blockIdx.y * TBM;
    const int n0 = blockIdx.x * TBN;

    float acc[TM][TN];
#pragma unroll
    for (int i = 0; i < TM; ++i)
#pragma unroll
        for (int j = 0; j < TN; ++j)
            acc[i][j] = 0.0f;

    // A-tile loader mapping: 128 rows x 16 cols, float4 chunks.
    const int arow = tid >> 2;          // 0..63 (two passes: +0, +64)
    const int acol = (tid & 3) * 4;     // 0,4,8,12

    // B-tile loader mapping for NN: 16 rows x 128 cols.
    const int brow = tid >> 5;          // 0..7 (two passes: +0, +8)
    const int bcol = (tid & 31) * 4;    // 0..124

    for (int k0 = 0; k0 < K; k0 += TBK) {
        // ---- load A tile (transposed into smem: As[k][m]) ----
#pragma unroll
        for (int p = 0; p < 2; ++p) {
            const int r = arow + p * 64;
            const float4 v = *(const float4*)(A + (long long)(m0 + r) * K + k0 + acol);
            As[acol + 0][r] = v.x;
            As[acol + 1][r] = v.y;
            As[acol + 2][r] = v.z;
            As[acol + 3][r] = v.w;
        }
        // ---- load B tile ----
        if (TRANS_B) {
            // B is [Ncols, K]; tile rows n0..n0+127, cols k0..k0+15 -> Bs[k][n]
#pragma unroll
            for (int p = 0; p < 2; ++p) {
                const int r = arow + p * 64;
                const float4 v = *(const float4*)(Bm + (long long)(n0 + r) * K + k0 + acol);
                Bs[acol + 0][r] = v.x;
                Bs[acol + 1][r] = v.y;
                Bs[acol + 2][r] = v.z;
                Bs[acol + 3][r] = v.w;
            }
        } else {
            // B is [K, Ncols]; tile rows k0..k0+15, cols n0..n0+127 -> Bs[k][n]
#pragma unroll
            for (int p = 0; p < 2; ++p) {
                const int r = brow + p * 8;
                const float4 v = *(const float4*)(Bm + (long long)(k0 + r) * Ncols + n0 + bcol);
                *(float4*)&Bs[r][bcol] = v;
            }
        }
        __syncthreads();

        // ---- compute ----
#pragma unroll
        for (int kk = 0; kk < TBK; ++kk) {
            float af[TM], bf[TN];
#pragma unroll
            for (int i = 0; i < TM; i += 4)
                *(float4*)&af[i] = *(const float4*)&As[kk][ty * TM + i];
#pragma unroll
            for (int j = 0; j < TN; j += 4)
                *(float4*)&bf[j] = *(const float4*)&Bs[kk][tx * TN + j];
#pragma unroll
            for (int i = 0; i < TM; ++i)
#pragma unroll
                for (int j = 0; j < TN; ++j)
                    acc[i][j] = fmaf(af[i], bf[j], acc[i][j]);
        }
        __syncthreads();
    }

    // ---- epilogue ----
#pragma unroll
    for (int i = 0; i < TM; ++i) {
        const long long row = m0 + ty * TM + i;
#pragma unroll
        for (int j = 0; j < TN; j += 4) {
            const int col = n0 + tx * TN + j;
            float4 v;
            v.x = acc[i][j + 0];
            v.y = acc[i][j + 1];
            v.z = acc[i][j + 2];
            v.w = acc[i][j + 3];
            if (HAS_BIAS) {
                v.x += bias[col + 0];
                v.y += bias[col + 1];
                v.z += bias[col + 2];
                v.w += bias[col + 3];
            }
            if (RELU) {
                v.x = fmaxf(v.x, 0.0f);
                v.y = fmaxf(v.y, 0.0f);
                v.z = fmaxf(v.z, 0.0f);
                v.w = fmaxf(v.w, 0.0f);
            }
            *(float4*)(C + row * Ncols + col) = v;
        }
    }
}

// ---------------------------------------------------------------------------
// Row softmax over contiguous rows of length Ncols. One block per row.
// ---------------------------------------------------------------------------
__global__ __launch_bounds__(256)
void softmax_rows_kernel(float* __restrict__ att, int Ncols)
{
    float* row = att + (long long)blockIdx.x * Ncols;
    __shared__ float red[256];
    const int tid = threadIdx.x;

    // max
    float m = -INFINITY;
    for (int j = tid; j < Ncols; j += 256) m = fmaxf(m, row[j]);
    red[tid] = m;
    __syncthreads();
#pragma unroll
    for (int s = 128; s > 0; s >>= 1) {
        if (tid < s) red[tid] = fmaxf(red[tid], red[tid + s]);
        __syncthreads();
    }
    m = red[0];
    __syncthreads();

    // exp + sum
    float sum = 0.0f;
    for (int j = tid; j < Ncols; j += 256) {
        const float e = __expf(row[j] - m);
        row[j] = e;
        sum += e;
    }
    red[tid] = sum;
    __syncthreads();
#pragma unroll
    for (int s = 128; s > 0; s >>= 1) {
        if (tid < s) red[tid] += red[tid + s];
        __syncthreads();
    }
    const float inv = 1.0f / red[0];
    __syncthreads();

    // normalize
    for (int j = tid; j < Ncols; j += 256) row[j] *= inv;
}

// ---------------------------------------------------------------------------
// Launch
// ---------------------------------------------------------------------------
extern "C" void kernel_launch(void* const* d_in, const int* in_sizes, int n_in,
                              void* d_out, int out_size)
{
    (void)in_sizes; (void)n_in; (void)out_size;
    // metadata order: d, h, Wv, bv, Wk, bk, Wq, bq, W1, b1, W2, b2
    const float* h  = (const float*)d_in[1];
    const float* Wv = (const float*)d_in[2];
    const float* bv = (const float*)d_in[3];
    const float* Wk = (const float*)d_in[4];
    const float* bk = (const float*)d_in[5];
    const float* Wq = (const float*)d_in[6];
    const float* bq = (const float*)d_in[7];
    const float* W1 = (const float*)d_in[8];
    const float* b1 = (const float*)d_in[9];
    const float* W2 = (const float*)d_in[10];
    const float* b2 = (const float*)d_in[11];
    float* out = (float*)d_out;

    float *q, *k, *v, *o, *hid, *att;
    cudaGetSymbolAddress((void**)&q,   g_q);
    cudaGetSymbolAddress((void**)&k,   g_k);
    cudaGetSymbolAddress((void**)&v,   g_v);
    cudaGetSymbolAddress((void**)&o,   g_o);
    cudaGetSymbolAddress((void**)&hid, g_hid);
    cudaGetSymbolAddress((void**)&att, g_att);

    const long long sQKV = (long long)NN_SEQ * HH;          // per-batch q/k/v stride
    const long long sATT = (long long)NN_SEQ * NN_SEQ;      // per-batch att stride

    // 1) q, k, v projections: [32768, 512] x [512, 512] + bias
    {
        dim3 grid(HH / TBN, BN_ROWS / TBM, 1);
        sgemm_kernel<false, true, false><<<grid, NTHREADS>>>(h, Wv, bv, v, BN_ROWS, HH, MM, 0, 0, 0);
        sgemm_kernel<false, true, false><<<grid, NTHREADS>>>(h, Wq, bq, q, BN_ROWS, HH, MM, 0, 0, 0);
        sgemm_kernel<false, true, false><<<grid, NTHREADS>>>(h, Wk, bk, k, BN_ROWS, HH, MM, 0, 0, 0);
    }

    // 2) logits: att[b] = q[b] @ k[b]^T   [2048 x 2048 x 512], batched over 16
    {
        dim3 grid(NN_SEQ / TBN, NN_SEQ / TBM, BB);
        sgemm_kernel<true, false, false><<<grid, NTHREADS>>>(q, k, nullptr, att,
                                                             NN_SEQ, NN_SEQ, HH,
                                                             sQKV, sQKV, sATT);
    }

    // 3) softmax over last dim
    softmax_rows_kernel<<<BN_ROWS, 256>>>(att, NN_SEQ);

    // 4) out: o[b] = att[b] @ v[b]   [2048 x 512 x 2048], batched over 16
    {
        dim3 grid(HH / TBN, NN_SEQ / TBM, BB);
        sgemm_kernel<false, false, false><<<grid, NTHREADS>>>(att, v, nullptr, o,
                                                              NN_SEQ, HH, NN_SEQ,
                                                              sATT, sQKV, sQKV);
    }

    // 5) hid = relu(o @ W1 + b1)   [32768, 512] x [512, 512]
    {
        dim3 grid(HH / TBN, BN_ROWS / TBM, 1);
        sgemm_kernel<false, true, true><<<grid, NTHREADS>>>(o, W1, b1, hid, BN_ROWS, HH, HH, 0, 0, 0);
    }

    // 6) out = hid @ W2 + b2   [32768, 512] x [512, 512] -> [B, N, M]
    {
        dim3 grid(MM / TBN, BN_ROWS / TBM, 1);
        sgemm_kernel<false, true, false><<<grid, NTHREADS>>>(hid, W2, b2, out, BN_ROWS, MM, HH, 0, 0, 0);
    }
}

// round 3
// speedup vs baseline: 1.9546x; 1.9546x over previous
#include <cuda_runtime.h>
#include <cuda_bf16.h>
#include <math.h>
#include <stdint.h>

// Problem dims (fixed)
#define BB 16
#define NSEQ 2048
#define MM 512
#define HH 512
#define BN_ROWS (BB * NSEQ)   // 32768

// ---------------------------------------------------------------------------
// Scratch (device globals; no runtime allocation allowed)
// ---------------------------------------------------------------------------
__device__ float g_q[BN_ROWS * HH];
__device__ float g_k[BN_ROWS * HH];
__device__ float g_v[BN_ROWS * HH];
__device__ float g_vt[BN_ROWS * HH];          // v transposed per batch: [B][H][N]
__device__ float g_o[BN_ROWS * HH];
__device__ float g_hid[BN_ROWS * HH];
__device__ float g_wt[5 * MM * HH];           // Wq^T, Wk^T, Wv^T, W1^T, W2^T
__device__ float g_att[(long long)BB * NSEQ * NSEQ];

// ---------------------------------------------------------------------------
// Helpers
// ---------------------------------------------------------------------------
__device__ __forceinline__ uint32_t smem_u32(const void* p) {
    uint32_t a;
    asm("{ .reg .u64 t; cvta.to.shared.u64 t, %1; cvt.u32.u64 %0, t; }" : "=r"(a) : "l"(p));
    return a;
}

__device__ __forceinline__ void ldsm4(uint32_t* r, uint32_t addr) {
    asm volatile("ldmatrix.sync.aligned.m8n8.x4.shared.b16 {%0,%1,%2,%3}, [%4];"
                 : "=r"(r[0]), "=r"(r[1]), "=r"(r[2]), "=r"(r[3]) : "r"(addr));
}

__device__ __forceinline__ void mma_bf16(float* c, const uint32_t* a, const uint32_t* b) {
    asm volatile(
        "mma.sync.aligned.m16n8k16.row.col.f32.bf16.bf16.f32 "
        "{%0,%1,%2,%3}, {%4,%5,%6,%7}, {%8,%9}, {%0,%1,%2,%3};"
        : "+f"(c[0]), "+f"(c[1]), "+f"(c[2]), "+f"(c[3])
        : "r"(a[0]), "r"(a[1]), "r"(a[2]), "r"(a[3]), "r"(b[0]), "r"(b[1]));
}

// ---------------------------------------------------------------------------
// HMMA NT GEMM with fp32 -> bf16 hi/lo split (3 MMAs per product).
// C[M,N] = A[M,K] @ B[N,K]^T (+bias)(relu). CTA tile 128x128, K staged 32.
// 8 warps as 4(m) x 2(n); warp tile 32x64.
// ---------------------------------------------------------------------------
#define PADK 40                       // 32 bf16 + 8 pad -> 80B row stride
#define STAGE_A (128 * PADK)          // bf16 elems per (operand, precision) tile
#define STAGE_ELEMS (4 * STAGE_A)     // aHi, aLo, bHi, bLo
#define SMEM_DYN (2 * STAGE_ELEMS * 2)  // bytes, double buffered = 81920

template <bool HAS_BIAS, bool RELU>
__global__ __launch_bounds__(256, 1)
void hmma_gemm(const float* __restrict__ A, const float* __restrict__ B,
               const float* __restrict__ bias, float* __restrict__ C,
               int K, int ldc, long long sA, long long sB, long long sC)
{
    extern __shared__ __nv_bfloat16 sm[];
    const long long bz = blockIdx.z;
    A += bz * sA;
    B += bz * sB;
    C += bz * sC;

    const int tid = threadIdx.x;
    const int wid = tid >> 5;
    const int lane = tid & 31;
    const int wm = wid & 3;          // 0..3 -> m offset 32*wm
    const int wn = wid >> 2;         // 0..1 -> n offset 64*wn
    const int lr = lane & 15;        // ldmatrix row within 16
    const int lc = lane >> 4;        // ldmatrix col half (+8)

    const int m0 = blockIdx.y * 128;
    const int n0 = blockIdx.x * 128;

    const int lrow = tid >> 1;           // loader row 0..127
    const int lkh = (tid & 1) * 16;      // loader k-half 0/16

    const uint32_t smb = smem_u32(sm);

    float acc[2][8][4];
#pragma unroll
    for (int i = 0; i < 2; ++i)
#pragma unroll
        for (int j = 0; j < 8; ++j)
#pragma unroll
            for (int t = 0; t < 4; ++t) acc[i][j][t] = 0.0f;

    const int S = K / 32;
    float ra[16], rb[16];

    const float* gA = A + (long long)(m0 + lrow) * K + lkh;
    const float* gB = B + (long long)(n0 + lrow) * K + lkh;

    // ---- prolog: load stage 0 ----
#pragma unroll
    for (int i = 0; i < 4; ++i) {
        *(float4*)&ra[i * 4] = *(const float4*)(gA + i * 4);
        *(float4*)&rb[i * 4] = *(const float4*)(gB + i * 4);
    }

    // convert+store helper (as macro over local arrays)
#define CVT_STORE(stage)                                                          \
    do {                                                                          \
        const int eoff = lrow * PADK + lkh;                                       \
        __nv_bfloat16* aH = sm + (stage) * STAGE_ELEMS + eoff;                    \
        uint32_t hi[8], lo[8];                                                    \
        _Pragma("unroll")                                                         \
        for (int i = 0; i < 8; ++i) {                                             \
            __nv_bfloat162 h = __floats2bfloat162_rn(ra[2*i], ra[2*i+1]);         \
            __nv_bfloat162 l = __floats2bfloat162_rn(ra[2*i] - __bfloat162float(h.x), \
                                                     ra[2*i+1] - __bfloat162float(h.y)); \
            hi[i] = *(uint32_t*)&h; lo[i] = *(uint32_t*)&l;                       \
        }                                                                         \
        *(uint4*)(aH)               = make_uint4(hi[0], hi[1], hi[2], hi[3]);     \
        *(uint4*)(aH + 8)           = make_uint4(hi[4], hi[5], hi[6], hi[7]);     \
        *(uint4*)(aH + STAGE_A)     = make_uint4(lo[0], lo[1], lo[2], lo[3]);     \
        *(uint4*)(aH + STAGE_A + 8) = make_uint4(lo[4], lo[5], lo[6], lo[7]);     \
        _Pragma("unroll")                                                         \
        for (int i = 0; i < 8; ++i) {                                             \
            __nv_bfloat162 h = __floats2bfloat162_rn(rb[2*i], rb[2*i+1]);         \
            __nv_bfloat162 l = __floats2bfloat162_rn(rb[2*i] - __bfloat162float(h.x), \
                                                     rb[2*i+1] - __bfloat162float(h.y)); \
            hi[i] = *(uint32_t*)&h; lo[i] = *(uint32_t*)&l;                       \
        }                                                                         \
        __nv_bfloat16* bH = aH + 2 * STAGE_A;                                     \
        *(uint4*)(bH)               = make_uint4(hi[0], hi[1], hi[2], hi[3]);     \
        *(uint4*)(bH + 8)           = make_uint4(hi[4], hi[5], hi[6], hi[7]);     \
        *(uint4*)(bH + STAGE_A)     = make_uint4(lo[0], lo[1], lo[2], lo[3]);     \
        *(uint4*)(bH + STAGE_A + 8) = make_uint4(lo[4], lo[5], lo[6], lo[7]);     \
    } while (0)

    CVT_STORE(0);
    __syncthreads();

    for (int s = 0; s < S; ++s) {
        const int cur = s & 1;

        // issue next-stage global loads early
        if (s + 1 < S) {
            const float* pa = gA + (s + 1) * 32;
            const float* pb = gB + (s + 1) * 32;
#pragma unroll
            for (int i = 0; i < 4; ++i) {
                *(float4*)&ra[i * 4] = *(const float4*)(pa + i * 4);
                *(float4*)&rb[i * 4] = *(const float4*)(pb + i * 4);
            }
        }

        // ---- compute current stage: 2 x k16 ----
        const uint32_t stA = smb + cur * (STAGE_ELEMS * 2);          // bytes
#pragma unroll
        for (int kk = 0; kk < 2; ++kk) {
            uint32_t aH[2][4], aL[2][4], bH[8][2], bL[8][2];
#pragma unroll
            for (int mi = 0; mi < 2; ++mi) {
                const uint32_t off = stA +
                    ((wm * 32 + mi * 16 + lr) * PADK + kk * 16 + lc * 8) * 2;
                ldsm4(aH[mi], off);
                ldsm4(aL[mi], off + STAGE_A * 2);
            }
#pragma unroll
            for (int g = 0; g < 4; ++g) {
                uint32_t r4[4];
                const uint32_t off = stA + 2 * STAGE_A * 2 +
                    ((wn * 64 + g * 16 + lr) * PADK + kk * 16 + lc * 8) * 2;
                ldsm4(r4, off);
                bH[2*g][0] = r4[0]; bH[2*g][1] = r4[2];
                bH[2*g+1][0] = r4[1]; bH[2*g+1][1] = r4[3];
                ldsm4(r4, off + STAGE_A * 2);
                bL[2*g][0] = r4[0]; bL[2*g][1] = r4[2];
                bL[2*g+1][0] = r4[1]; bL[2*g+1][1] = r4[3];
            }
#pragma unroll
            for (int mi = 0; mi < 2; ++mi)
#pragma unroll
                for (int nj = 0; nj < 8; ++nj) {
                    mma_bf16(acc[mi][nj], aH[mi], bH[nj]);
                    mma_bf16(acc[mi][nj], aH[mi], bL[nj]);
                    mma_bf16(acc[mi][nj], aL[mi], bH[nj]);
                }
        }

        if (s + 1 < S) CVT_STORE((s + 1) & 1);
        __syncthreads();
    }

    // ---- epilogue ----
#pragma unroll
    for (int mi = 0; mi < 2; ++mi) {
        const int r0 = m0 + wm * 32 + mi * 16 + (lane >> 2);
#pragma unroll
        for (int nj = 0; nj < 8; ++nj) {
            const int col = n0 + wn * 64 + nj * 8 + 2 * (lane & 3);
            float bx = 0.0f, by = 0.0f;
            if (HAS_BIAS) {
                const float2 bv = *(const float2*)(bias + col);
                bx = bv.x; by = bv.y;
            }
            float x0 = acc[mi][nj][0] + bx;
            float x1 = acc[mi][nj][1] + by;
            float x2 = acc[mi][nj][2] + bx;
            float x3 = acc[mi][nj][3] + by;
            if (RELU) {
                x0 = fmaxf(x0, 0.0f); x1 = fmaxf(x1, 0.0f);
                x2 = fmaxf(x2, 0.0f); x3 = fmaxf(x3, 0.0f);
            }
            *(float2*)(C + (long long)r0 * ldc + col) = make_float2(x0, x1);
            *(float2*)(C + (long long)(r0 + 8) * ldc + col) = make_float2(x2, x3);
        }
    }
#undef CVT_STORE
}

// ---------------------------------------------------------------------------
// Transpose: out[c][r] = in[r][c]. Grid: (C/32, R/32, batches), block 32x8.
// ---------------------------------------------------------------------------
__global__ __launch_bounds__(256)
void transpose_kernel(const float* __restrict__ in, float* __restrict__ out,
                      int R, int C, long long sIn, long long sOut)
{
    __shared__ float t[32][33];
    in += blockIdx.z * sIn;
    out += blockIdx.z * sOut;
    const int c0 = blockIdx.x * 32;
    const int r0 = blockIdx.y * 32;
    const int x = threadIdx.x;
    const int y = threadIdx.y;
#pragma unroll
    for (int j = 0; j < 32; j += 8)
        t[y + j][x] = in[(long long)(r0 + y + j) * C + c0 + x];
    __syncthreads();
#pragma unroll
    for (int j = 0; j < 32; j += 8)
        out[(long long)(c0 + y + j) * R + r0 + x] = t[x][y + j];
}

// ---------------------------------------------------------------------------
// Row softmax (length 2048), row cached in registers. One block per row.
// ---------------------------------------------------------------------------
__global__ __launch_bounds__(256)
void softmax_rows_kernel(float* __restrict__ att)
{
    float* row = att + (long long)blockIdx.x * NSEQ;
    __shared__ float red[256];
    const int tid = threadIdx.x;

    float r[8];
#pragma unroll
    for (int p = 0; p < 8; ++p) r[p] = row[tid + p * 256];

    float m = r[0];
#pragma unroll
    for (int p = 1; p < 8; ++p) m = fmaxf(m, r[p]);
    red[tid] = m;
    __syncthreads();
#pragma unroll
    for (int s = 128; s > 0; s >>= 1) {
        if (tid < s) red[tid] = fmaxf(red[tid], red[tid + s]);
        __syncthreads();
    }
    m = red[0];
    __syncthreads();

    float sum = 0.0f;
#pragma unroll
    for (int p = 0; p < 8; ++p) {
        r[p] = __expf(r[p] - m);
        sum += r[p];
    }
    red[tid] = sum;
    __syncthreads();
#pragma unroll
    for (int s = 128; s > 0; s >>= 1) {
        if (tid < s) red[tid] += red[tid + s];
        __syncthreads();
    }
    const float inv = 1.0f / red[0];

#pragma unroll
    for (int p = 0; p < 8; ++p) row[tid + p * 256] = r[p] * inv;
}

// ---------------------------------------------------------------------------
// Launch
// ---------------------------------------------------------------------------
extern "C" void kernel_launch(void* const* d_in, const int* in_sizes, int n_in,
                              void* d_out, int out_size)
{
    (void)in_sizes; (void)n_in; (void)out_size;
    // metadata order: d, h, Wv, bv, Wk, bk, Wq, bq, W1, b1, W2, b2
    const float* h  = (const float*)d_in[1];
    const float* Wv = (const float*)d_in[2];
    const float* bv = (const float*)d_in[3];
    const float* Wk = (const float*)d_in[4];
    const float* bk = (const float*)d_in[5];
    const float* Wq = (const float*)d_in[6];
    const float* bq = (const float*)d_in[7];
    const float* W1 = (const float*)d_in[8];
    const float* b1 = (const float*)d_in[9];
    const float* W2 = (const float*)d_in[10];
    const float* b2 = (const float*)d_in[11];
    float* out = (float*)d_out;

    float *q, *k, *v, *vt, *o, *hid, *wt, *att;
    cudaGetSymbolAddress((void**)&q,   g_q);
    cudaGetSymbolAddress((void**)&k,   g_k);
    cudaGetSymbolAddress((void**)&v,   g_v);
    cudaGetSymbolAddress((void**)&vt,  g_vt);
    cudaGetSymbolAddress((void**)&o,   g_o);
    cudaGetSymbolAddress((void**)&hid, g_hid);
    cudaGetSymbolAddress((void**)&wt,  g_wt);
    cudaGetSymbolAddress((void**)&att, g_att);

    cudaFuncSetAttribute(hmma_gemm<false, false>, cudaFuncAttributeMaxDynamicSharedMemorySize, SMEM_DYN);
    cudaFuncSetAttribute(hmma_gemm<true,  false>, cudaFuncAttributeMaxDynamicSharedMemorySize, SMEM_DYN);
    cudaFuncSetAttribute(hmma_gemm<true,  true >, cudaFuncAttributeMaxDynamicSharedMemorySize, SMEM_DYN);

    float* wtq = wt + 0 * MM * HH;
    float* wtk = wt + 1 * MM * HH;
    float* wtv = wt + 2 * MM * HH;
    float* wt1 = wt + 3 * MM * HH;
    float* wt2 = wt + 4 * MM * HH;

    const long long sQKV = (long long)NSEQ * HH;
    const long long sATT = (long long)NSEQ * NSEQ;

    // 0) transpose the 5 weight matrices (512x512 each)
    {
        dim3 blk(32, 8);
        dim3 grd(HH / 32, MM / 32, 1);
        transpose_kernel<<<grd, blk>>>(Wq, wtq, MM, HH, 0, 0);
        transpose_kernel<<<grd, blk>>>(Wk, wtk, MM, HH, 0, 0);
        transpose_kernel<<<grd, blk>>>(Wv, wtv, MM, HH, 0, 0);
        transpose_kernel<<<grd, blk>>>(W1, wt1, HH, HH, 0, 0);
        transpose_kernel<<<grd, blk>>>(W2, wt2, HH, MM, 0, 0);
    }

    // 1) q, k, v projections: [32768,512] = h @ Wt^T (NT, bias)
    {
        dim3 grd(HH / 128, BN_ROWS / 128, 1);
        hmma_gemm<true, false><<<grd, 256, SMEM_DYN>>>(h, wtq, bq, q, MM, HH, 0, 0, 0);
        hmma_gemm<true, false><<<grd, 256, SMEM_DYN>>>(h, wtk, bk, k, MM, HH, 0, 0, 0);
        hmma_gemm<true, false><<<grd, 256, SMEM_DYN>>>(h, wtv, bv, v, MM, HH, 0, 0, 0);
    }

    // 2) transpose v per batch: [2048,512] -> [512,2048]
    {
        dim3 blk(32, 8);
        dim3 grd(HH / 32, NSEQ / 32, BB);
        transpose_kernel<<<grd, blk>>>(v, vt, NSEQ, HH, sQKV, sQKV);
    }

    // 3) logits: att[b] = q[b] @ k[b]^T (batched NT)
    {
        dim3 grd(NSEQ / 128, NSEQ / 128, BB);
        hmma_gemm<false, false><<<grd, 256, SMEM_DYN>>>(q, k, nullptr, att,
                                                        HH, NSEQ, sQKV, sQKV, sATT);
    }

    // 4) softmax
    softmax_rows_kernel<<<BN_ROWS, 256>>>(att);

    // 5) o[b] = att[b] @ vt[b]^T  (K = 2048)
    {
        dim3 grd(HH / 128, NSEQ / 128, BB);
        hmma_gemm<false, false><<<grd, 256, SMEM_DYN>>>(att, vt, nullptr, o,
                                                        NSEQ, HH, sATT, sQKV, sQKV);
    }

    // 6) hid = relu(o @ W1t^T + b1)
    {
        dim3 grd(HH / 128, BN_ROWS / 128, 1);
        hmma_gemm<true, true><<<grd, 256, SMEM_DYN>>>(o, wt1, b1, hid, HH, HH, 0, 0, 0);
    }

    // 7) out = hid @ W2t^T + b2
    {
        dim3 grd(MM / 128, BN_ROWS / 128, 1);
        hmma_gemm<true, false><<<grd, 256, SMEM_DYN>>>(hid, wt2, b2, out, HH, MM, 0, 0, 0);
    }
}

// round 4
// speedup vs baseline: 2.2564x; 1.1544x over previous
#include <cuda_runtime.h>
#include <cuda_bf16.h>
#include <math.h>
#include <stdint.h>

// Problem dims (fixed)
#define BB 16
#define NSEQ 2048
#define MM 512
#define HH 512
#define BN_ROWS (BB * NSEQ)   // 32768

// ---------------------------------------------------------------------------
// Split layout: for a logical [R x K] fp32 matrix, store 4 bytes/elem as
// groups of 32 columns: each 128B group = 32 bf16 "hi" then 32 bf16 "lo".
// byte(r, c) = r*rowBytes + (c>>5)*128 + (c&31)*2   (hi; lo at +64)
// ---------------------------------------------------------------------------
__device__ __align__(128) uint8_t g_h_s  [(long long)BN_ROWS * HH * 4];
__device__ __align__(128) uint8_t g_qkv_s[(long long)BN_ROWS * 1536 * 4];
__device__ __align__(128) uint8_t g_vt_s [(long long)BN_ROWS * HH * 4];
__device__ __align__(128) uint8_t g_o_s  [(long long)BN_ROWS * HH * 4];
__device__ __align__(128) uint8_t g_hid_s[(long long)BN_ROWS * HH * 4];
__device__ __align__(128) uint8_t g_w_s  [(long long)(1536 + 512 + 512) * 512 * 4];
__device__ float g_att[(long long)BB * NSEQ * NSEQ];
__device__ __align__(128) uint8_t g_att_s[(long long)BB * NSEQ * NSEQ * 4];
__device__ float g_bqkv[1536];

// ---------------------------------------------------------------------------
// Helpers
// ---------------------------------------------------------------------------
__device__ __forceinline__ uint32_t smem_u32(const void* p) {
    uint32_t a;
    asm("{ .reg .u64 t; cvta.to.shared.u64 t, %1; cvt.u32.u64 %0, t; }" : "=r"(a) : "l"(p));
    return a;
}
__device__ __forceinline__ void ldsm4(uint32_t* r, uint32_t addr) {
    asm volatile("ldmatrix.sync.aligned.m8n8.x4.shared.b16 {%0,%1,%2,%3}, [%4];"
                 : "=r"(r[0]), "=r"(r[1]), "=r"(r[2]), "=r"(r[3]) : "r"(addr));
}
__device__ __forceinline__ void mma_bf16(float* c, const uint32_t* a,
                                         uint32_t b0, uint32_t b1) {
    asm volatile(
        "mma.sync.aligned.m16n8k16.row.col.f32.bf16.bf16.f32 "
        "{%0,%1,%2,%3}, {%4,%5,%6,%7}, {%8,%9}, {%0,%1,%2,%3};"
        : "+f"(c[0]), "+f"(c[1]), "+f"(c[2]), "+f"(c[3])
        : "r"(a[0]), "r"(a[1]), "r"(a[2]), "r"(a[3]), "r"(b0), "r"(b1));
}
__device__ __forceinline__ void cp16(uint32_t dst, const void* src) {
    asm volatile("cp.async.cg.shared.global [%0], [%1], 16;" :: "r"(dst), "l"(src));
}
__device__ __forceinline__ void cp_commit() {
    asm volatile("cp.async.commit_group;");
}
template <int N> __device__ __forceinline__ void cp_wait() {
    asm volatile("cp.async.wait_group %0;" :: "n"(N));
}
__device__ __forceinline__ void split2(float x, float y, uint32_t& hi, uint32_t& lo) {
    __nv_bfloat162 h = __floats2bfloat162_rn(x, y);
    __nv_bfloat162 l = __floats2bfloat162_rn(x - __bfloat162float(h.x),
                                             y - __bfloat162float(h.y));
    hi = *(uint32_t*)&h;
    lo = *(uint32_t*)&l;
}

// ---------------------------------------------------------------------------
// HMMA NT GEMM on pre-split bf16 hi/lo operands (3 MMAs per product).
// C[M,N] = A[M,K] @ B[N,K]^T (+bias)(relu).
// CTA tile 128x128, K staged 32, cp.async 3-stage pipeline.
// smem per stage: A 128x128B (SW128 xor swizzle) + B 128x128B = 32KB.
// ---------------------------------------------------------------------------
#define STAGES 3
#define STAGE_BYTES 32768
#define SMEM_DYN (STAGES * STAGE_BYTES)   // 98304

template <bool HAS_BIAS, bool RELU, bool F32OUT>
__global__ __launch_bounds__(256, 2)
void hmma_gemm(const uint8_t* __restrict__ A, const uint8_t* __restrict__ B,
               const float* __restrict__ bias, float* __restrict__ Cf,
               uint8_t* __restrict__ Cs,
               int K, long long ldaB, long long ldbB, long long ldcB,
               long long sA, long long sB, long long sC)
{
    extern __shared__ uint8_t sm[];
    const long long bz = blockIdx.z;
    A += bz * sA;
    B += bz * sB;

    const int tid = threadIdx.x;
    const int wid = tid >> 5;
    const int lane = tid & 31;
    const int wm = wid & 3;
    const int wn = wid >> 2;
    const int lr = lane & 15;
    const int lc = lane >> 4;

    const int m0 = blockIdx.y * 128;
    const int n0 = blockIdx.x * 128;

    const int lrow = tid >> 1;          // 0..127
    const int cb = (tid & 1) * 4;       // chunk base 0 or 4
    const int rsw = lrow & 7;

    const uint32_t smb = smem_u32(sm);
    const uint8_t* srcA0 = A + (long long)(m0 + lrow) * ldaB + cb * 16;
    const uint8_t* srcB0 = B + (long long)(n0 + lrow) * ldbB + cb * 16;

    float acc[2][8][4];
#pragma unroll
    for (int i = 0; i < 2; ++i)
#pragma unroll
        for (int j = 0; j < 8; ++j)
#pragma unroll
            for (int t = 0; t < 4; ++t) acc[i][j][t] = 0.0f;

    const int S = K / 32;

#define ISSUE_STAGE(s)                                                        \
    do {                                                                      \
        const uint32_t dra = smb + ((s) % STAGES) * STAGE_BYTES + lrow * 128; \
        const uint8_t* pa = srcA0 + (s) * 128;                                \
        const uint8_t* pb = srcB0 + (s) * 128;                                \
        _Pragma("unroll")                                                     \
        for (int c = 0; c < 4; ++c)                                           \
            cp16(dra + (((cb + c) ^ rsw) << 4), pa + c * 16);                 \
        _Pragma("unroll")                                                     \
        for (int c = 0; c < 4; ++c)                                           \
            cp16(dra + 16384 + (((cb + c) ^ rsw) << 4), pb + c * 16);         \
        cp_commit();                                                          \
    } while (0)

    ISSUE_STAGE(0);
    ISSUE_STAGE(1);

    for (int s = 0; s < S; ++s) {
        if (s + 1 < S) cp_wait<1>(); else cp_wait<0>();
        __syncthreads();
        if (s + 2 < S) ISSUE_STAGE(s + 2);

        const uint32_t bufA = smb + (s % STAGES) * STAGE_BYTES;
        const uint32_t bufB = bufA + 16384;

#pragma unroll
        for (int kk = 0; kk < 2; ++kk) {
            uint32_t aH[2][4], aL[2][4];
#pragma unroll
            for (int mi = 0; mi < 2; ++mi) {
                const int r = wm * 32 + mi * 16 + lr;
                const int byteh = kk * 32 + lc * 16;
                const uint32_t rb = bufA + r * 128;
                const int rs = r & 7;
                ldsm4(aH[mi], rb + ((((byteh) >> 4) ^ rs) << 4));
                ldsm4(aL[mi], rb + ((((byteh + 64) >> 4) ^ rs) << 4));
            }
#pragma unroll
            for (int g = 0; g < 4; ++g) {
                const int r = wn * 64 + g * 16 + lr;
                const int byteh = kk * 32 + lc * 16;
                const uint32_t rb = bufB + r * 128;
                const int rs = r & 7;
                uint32_t bh[4], bl[4];
                ldsm4(bh, rb + ((((byteh) >> 4) ^ rs) << 4));
                ldsm4(bl, rb + ((((byteh + 64) >> 4) ^ rs) << 4));
#pragma unroll
                for (int mi = 0; mi < 2; ++mi) {
                    mma_bf16(acc[mi][2 * g],     aH[mi], bh[0], bh[2]);
                    mma_bf16(acc[mi][2 * g],     aH[mi], bl[0], bl[2]);
                    mma_bf16(acc[mi][2 * g],     aL[mi], bh[0], bh[2]);
                    mma_bf16(acc[mi][2 * g + 1], aH[mi], bh[1], bh[3]);
                    mma_bf16(acc[mi][2 * g + 1], aH[mi], bl[1], bl[3]);
                    mma_bf16(acc[mi][2 * g + 1], aL[mi], bh[1], bh[3]);
                }
            }
        }
    }
#undef ISSUE_STAGE

    // ---- epilogue ----
#pragma unroll
    for (int mi = 0; mi < 2; ++mi) {
        const long long r0 = m0 + wm * 32 + mi * 16 + (lane >> 2);
#pragma unroll
        for (int nj = 0; nj < 8; ++nj) {
            const int col = n0 + wn * 64 + nj * 8 + 2 * (lane & 3);
            float bx = 0.0f, by = 0.0f;
            if (HAS_BIAS) {
                const float2 bvv = *(const float2*)(bias + col);
                bx = bvv.x; by = bvv.y;
            }
            float x0 = acc[mi][nj][0] + bx;
            float x1 = acc[mi][nj][1] + by;
            float x2 = acc[mi][nj][2] + bx;
            float x3 = acc[mi][nj][3] + by;
            if (RELU) {
                x0 = fmaxf(x0, 0.0f); x1 = fmaxf(x1, 0.0f);
                x2 = fmaxf(x2, 0.0f); x3 = fmaxf(x3, 0.0f);
            }
            if (F32OUT) {
                uint8_t* base = (uint8_t*)Cf + bz * sC;
                *(float2*)(base + r0 * ldcB + col * 4)       = make_float2(x0, x1);
                *(float2*)(base + (r0 + 8) * ldcB + col * 4) = make_float2(x2, x3);
            } else {
                uint8_t* base = Cs + bz * sC;
                const long long cb0 = (long long)(col >> 5) * 128 + (col & 31) * 2;
                uint32_t hi, lo;
                split2(x0, x1, hi, lo);
                uint8_t* p = base + r0 * ldcB + cb0;
                *(uint32_t*)p = hi;
                *(uint32_t*)(p + 64) = lo;
                split2(x2, x3, hi, lo);
                p = base + (r0 + 8) * ldcB + cb0;
                *(uint32_t*)p = hi;
                *(uint32_t*)(p + 64) = lo;
            }
        }
    }
}

// ---------------------------------------------------------------------------
// fp32 -> split (no transpose). Row length fixed 512. 8 elems/thread.
// ---------------------------------------------------------------------------
__global__ __launch_bounds__(256)
void split_rows512(const float* __restrict__ in, uint8_t* __restrict__ out)
{
    const long long i8 = ((long long)blockIdx.x * 256 + threadIdx.x) * 8;
    const long long row = i8 >> 9;
    const int col = (int)(i8 & 511);
    const float4 a = *(const float4*)(in + i8);
    const float4 b = *(const float4*)(in + i8 + 4);
    uint4 hi, lo;
    split2(a.x, a.y, hi.x, lo.x);
    split2(a.z, a.w, hi.y, lo.y);
    split2(b.x, b.y, hi.z, lo.z);
    split2(b.z, b.w, hi.w, lo.w);
    uint8_t* p = out + row * 2048 + (col >> 5) * 128 + (col & 31) * 2;
    *(uint4*)p = hi;
    *(uint4*)(p + 64) = lo;
}

// ---------------------------------------------------------------------------
// Weight transpose + split: in fp32 [R][C]; out split rows=C (at rowOff), cols=R.
// out row bytes = R*4 (=2048 for R=512).
// ---------------------------------------------------------------------------
__global__ __launch_bounds__(256)
void transpose_split_w(const float* __restrict__ in, uint8_t* __restrict__ out,
                       int R, int C, long long rowOff)
{
    __shared__ float t[32][33];
    const int c0 = blockIdx.x * 32;
    const int r0 = blockIdx.y * 32;
    const int x = threadIdx.x;
    const int y = threadIdx.y;
#pragma unroll
    for (int j = 0; j < 32; j += 8)
        t[y + j][x] = in[(long long)(r0 + y + j) * C + c0 + x];
    __syncthreads();
#pragma unroll
    for (int j = 0; j < 32; j += 8) {
        const float val = t[x][y + j];
        const long long row = rowOff + c0 + y + j;
        const int col = r0 + x;
        __nv_bfloat16 hi = __float2bfloat16(val);
        __nv_bfloat16 lo = __float2bfloat16(val - __bfloat162float(hi));
        uint8_t* p = out + row * ((long long)R * 4) + (col >> 5) * 128 + (col & 31) * 2;
        *(__nv_bfloat16*)p = hi;
        *(__nv_bfloat16*)(p + 64) = lo;
    }
}

// ---------------------------------------------------------------------------
// v^T: read v from qkv split (col offset 1024, row bytes 6144), write vt split
// per batch [512 rows][2048 cols] (row bytes 8192).
// ---------------------------------------------------------------------------
__global__ __launch_bounds__(256)
void vt_transpose(const uint8_t* __restrict__ qkv, uint8_t* __restrict__ vt)
{
    __shared__ float t[32][33];
    const long long b = blockIdx.z;
    const int h0 = blockIdx.x * 32;
    const int n0 = blockIdx.y * 32;
    const int x = threadIdx.x;
    const int y = threadIdx.y;
#pragma unroll
    for (int j = 0; j < 32; j += 8) {
        const long long row = b * 2048 + n0 + y + j;
        const int col = 1024 + h0 + x;
        const uint8_t* p = qkv + row * 6144 + (col >> 5) * 128 + (col & 31) * 2;
        t[y + j][x] = __bfloat162float(*(const __nv_bfloat16*)p) +
                      __bfloat162float(*(const __nv_bfloat16*)(p + 64));
    }
    __syncthreads();
#pragma unroll
    for (int j = 0; j < 32; j += 8) {
        const float val = t[x][y + j];
        const long long row = h0 + y + j;
        const int col = n0 + x;
        __nv_bfloat16 hi = __float2bfloat16(val);
        __nv_bfloat16 lo = __float2bfloat16(val - __bfloat162float(hi));
        uint8_t* p = vt + b * (512LL * 8192) + row * 8192 + (col >> 5) * 128 + (col & 31) * 2;
        *(__nv_bfloat16*)p = hi;
        *(__nv_bfloat16*)(p + 64) = lo;
    }
}

// ---------------------------------------------------------------------------
// Row softmax (2048) reading fp32, writing split. One block per row.
// Thread t handles 8 contiguous cols [t*8, t*8+8).
// ---------------------------------------------------------------------------
__global__ __launch_bounds__(256)
void softmax_split_kernel(const float* __restrict__ att, uint8_t* __restrict__ outs)
{
    const float* row = att + (long long)blockIdx.x * NSEQ;
    uint8_t* orow = outs + (long long)blockIdx.x * 8192;
    __shared__ float red[256];
    const int tid = threadIdx.x;
    const int c0 = tid * 8;

    float r[8];
    *(float4*)&r[0] = *(const float4*)(row + c0);
    *(float4*)&r[4] = *(const float4*)(row + c0 + 4);

    float m = r[0];
#pragma unroll
    for (int p = 1; p < 8; ++p) m = fmaxf(m, r[p]);
    red[tid] = m;
    __syncthreads();
#pragma unroll
    for (int s = 128; s > 0; s >>= 1) {
        if (tid < s) red[tid] = fmaxf(red[tid], red[tid + s]);
        __syncthreads();
    }
    m = red[0];
    __syncthreads();

    float sum = 0.0f;
#pragma unroll
    for (int p = 0; p < 8; ++p) {
        r[p] = __expf(r[p] - m);
        sum += r[p];
    }
    red[tid] = sum;
    __syncthreads();
#pragma unroll
    for (int s = 128; s > 0; s >>= 1) {
        if (tid < s) red[tid] += red[tid + s];
        __syncthreads();
    }
    const float inv = 1.0f / red[0];

    uint4 hi, lo;
    split2(r[0] * inv, r[1] * inv, hi.x, lo.x);
    split2(r[2] * inv, r[3] * inv, hi.y, lo.y);
    split2(r[4] * inv, r[5] * inv, hi.z, lo.z);
    split2(r[6] * inv, r[7] * inv, hi.w, lo.w);
    uint8_t* p = orow + (c0 >> 5) * 128 + (c0 & 31) * 2;
    *(uint4*)p = hi;
    *(uint4*)(p + 64) = lo;
}

__global__ void concat_bias(const float* bq, const float* bk, const float* bv,
                            float* dst)
{
    const int t = blockIdx.x * 256 + threadIdx.x;
    if (t < 512) {
        dst[t] = bq[t];
        dst[512 + t] = bk[t];
        dst[1024 + t] = bv[t];
    }
}

// ---------------------------------------------------------------------------
// Launch
// ---------------------------------------------------------------------------
extern "C" void kernel_launch(void* const* d_in, const int* in_sizes, int n_in,
                              void* d_out, int out_size)
{
    (void)in_sizes; (void)n_in; (void)out_size;
    const float* h  = (const float*)d_in[1];
    const float* Wv = (const float*)d_in[2];
    const float* bv = (const float*)d_in[3];
    const float* Wk = (const float*)d_in[4];
    const float* bk = (const float*)d_in[5];
    const float* Wq = (const float*)d_in[6];
    const float* bq = (const float*)d_in[7];
    const float* W1 = (const float*)d_in[8];
    const float* b1 = (const float*)d_in[9];
    const float* W2 = (const float*)d_in[10];
    const float* b2 = (const float*)d_in[11];
    float* out = (float*)d_out;

    uint8_t *hs, *qkvs, *vts, *os, *hids, *ws, *atts;
    float *att, *bqkv;
    cudaGetSymbolAddress((void**)&hs,   g_h_s);
    cudaGetSymbolAddress((void**)&qkvs, g_qkv_s);
    cudaGetSymbolAddress((void**)&vts,  g_vt_s);
    cudaGetSymbolAddress((void**)&os,   g_o_s);
    cudaGetSymbolAddress((void**)&hids, g_hid_s);
    cudaGetSymbolAddress((void**)&ws,   g_w_s);
    cudaGetSymbolAddress((void**)&att,  g_att);
    cudaGetSymbolAddress((void**)&atts, g_att_s);
    cudaGetSymbolAddress((void**)&bqkv, g_bqkv);

    cudaFuncSetAttribute(hmma_gemm<true,  false, false>, cudaFuncAttributeMaxDynamicSharedMemorySize, SMEM_DYN);
    cudaFuncSetAttribute(hmma_gemm<false, false, true >, cudaFuncAttributeMaxDynamicSharedMemorySize, SMEM_DYN);
    cudaFuncSetAttribute(hmma_gemm<false, false, false>, cudaFuncAttributeMaxDynamicSharedMemorySize, SMEM_DYN);
    cudaFuncSetAttribute(hmma_gemm<true,  true,  false>, cudaFuncAttributeMaxDynamicSharedMemorySize, SMEM_DYN);
    cudaFuncSetAttribute(hmma_gemm<true,  false, true >, cudaFuncAttributeMaxDynamicSharedMemorySize, SMEM_DYN);

    uint8_t* wqkv = ws;                                  // 1536 rows x 2048B
    uint8_t* w1t  = ws + 1536LL * 2048;                  // 512 rows
    uint8_t* w2t  = ws + 2048LL * 2048;                  // 512 rows

    // 0) prep: bias concat, weight transpose+split, h split
    concat_bias<<<2, 256>>>(bq, bk, bv, bqkv);
    {
        dim3 blk(32, 8), grd(16, 16);
        transpose_split_w<<<grd, blk>>>(Wq, wqkv, 512, 512, 0);
        transpose_split_w<<<grd, blk>>>(Wk, wqkv, 512, 512, 512);
        transpose_split_w<<<grd, blk>>>(Wv, wqkv, 512, 512, 1024);
        transpose_split_w<<<grd, blk>>>(W1, w1t, 512, 512, 0);
        transpose_split_w<<<grd, blk>>>(W2, w2t, 512, 512, 0);
    }
    split_rows512<<<(BN_ROWS * 512 / 8) / 256, 256>>>(h, hs);

    // 1) fused QKV: [32768,1536] = h @ wqkv^T + bqkv  -> qkv split (ldc 6144B)
    {
        dim3 grd(1536 / 128, BN_ROWS / 128, 1);
        hmma_gemm<true, false, false><<<grd, 256, SMEM_DYN>>>(
            hs, wqkv, bqkv, nullptr, qkvs, 512, 2048, 2048, 6144, 0, 0, 0);
    }

    // 2) v^T per batch
    {
        dim3 blk(32, 8), grd(512 / 32, 2048 / 32, BB);
        vt_transpose<<<grd, blk>>>(qkvs, vts);
    }

    // 3) logits: att[b] = q @ k^T  (fp32 out)
    {
        dim3 grd(NSEQ / 128, NSEQ / 128, BB);
        hmma_gemm<false, false, true><<<grd, 256, SMEM_DYN>>>(
            qkvs, qkvs + 2048, nullptr, att, nullptr,
            512, 6144, 6144, 8192,
            2048LL * 6144, 2048LL * 6144, 2048LL * 8192);
    }

    // 4) softmax -> att split
    softmax_split_kernel<<<BN_ROWS, 256>>>(att, atts);

    // 5) o[b] = att @ vt^T  (K=2048) -> o split
    {
        dim3 grd(HH / 128, NSEQ / 128, BB);
        hmma_gemm<false, false, false><<<grd, 256, SMEM_DYN>>>(
            atts, vts, nullptr, nullptr, os,
            2048, 8192, 8192, 2048,
            2048LL * 8192, 512LL * 8192, 2048LL * 2048);
    }

    // 6) hid = relu(o @ w1t^T + b1) -> hid split
    {
        dim3 grd(HH / 128, BN_ROWS / 128, 1);
        hmma_gemm<true, true, false><<<grd, 256, SMEM_DYN>>>(
            os, w1t, b1, nullptr, hids, 512, 2048, 2048, 2048, 0, 0, 0);
    }

    // 7) out = hid @ w2t^T + b2  (fp32 out)
    {
        dim3 grd(MM / 128, BN_ROWS / 128, 1);
        hmma_gemm<true, false, true><<<grd, 256, SMEM_DYN>>>(
            hids, w2t, b2, out, nullptr, 512, 2048, 2048, 2048, 0, 0, 0);
    }
}

// round 5
// speedup vs baseline: 2.4838x; 1.1008x over previous
#include <cuda_runtime.h>
#include <cuda_bf16.h>
#include <cuda_fp16.h>
#include <math.h>
#include <stdint.h>

// Problem dims (fixed)
#define BB 16
#define NSEQ 2048
#define MM 512
#define HH 512
#define BN_ROWS (BB * NSEQ)   // 32768

// ---------------------------------------------------------------------------
// Split layout: for a logical [R x K] matrix, store 4 bytes/elem as groups of
// 32 columns: each 128B group = 32 x 2B "hi" then 32 x 2B "lo".
// byte(r, c) = r*rowBytes + (c>>5)*128 + (c&31)*2   (hi; lo at +64)
// ---------------------------------------------------------------------------
__device__ __align__(128) uint8_t g_h_s  [(long long)BN_ROWS * HH * 4];
__device__ __align__(128) uint8_t g_qkv_s[(long long)BN_ROWS * 1536 * 4];
__device__ __align__(128) uint8_t g_vt_s [(long long)BN_ROWS * HH * 4];   // fp16 split
__device__ __align__(128) uint8_t g_o_s  [(long long)BN_ROWS * HH * 4];
__device__ __align__(128) uint8_t g_hid_s[(long long)BN_ROWS * HH * 4];
__device__ __align__(128) uint8_t g_w_s  [(long long)(1536 + 512 + 512) * 512 * 4];
__device__ float g_att[(long long)BB * NSEQ * NSEQ];
__device__ __align__(128) __half g_atth[(long long)BB * NSEQ * NSEQ];     // fp16 plain
__device__ float g_bqkv[1536];

// ---------------------------------------------------------------------------
// Helpers
// ---------------------------------------------------------------------------
__device__ __forceinline__ uint32_t smem_u32(const void* p) {
    uint32_t a;
    asm("{ .reg .u64 t; cvta.to.shared.u64 t, %1; cvt.u32.u64 %0, t; }" : "=r"(a) : "l"(p));
    return a;
}
__device__ __forceinline__ void ldsm4(uint32_t* r, uint32_t addr) {
    asm volatile("ldmatrix.sync.aligned.m8n8.x4.shared.b16 {%0,%1,%2,%3}, [%4];"
                 : "=r"(r[0]), "=r"(r[1]), "=r"(r[2]), "=r"(r[3]) : "r"(addr));
}
__device__ __forceinline__ void mma_bf16(float* c, const uint32_t* a,
                                         uint32_t b0, uint32_t b1) {
    asm volatile(
        "mma.sync.aligned.m16n8k16.row.col.f32.bf16.bf16.f32 "
        "{%0,%1,%2,%3}, {%4,%5,%6,%7}, {%8,%9}, {%0,%1,%2,%3};"
        : "+f"(c[0]), "+f"(c[1]), "+f"(c[2]), "+f"(c[3])
        : "r"(a[0]), "r"(a[1]), "r"(a[2]), "r"(a[3]), "r"(b0), "r"(b1));
}
__device__ __forceinline__ void mma_f16(float* c, const uint32_t* a,
                                        uint32_t b0, uint32_t b1) {
    asm volatile(
        "mma.sync.aligned.m16n8k16.row.col.f32.f16.f16.f32 "
        "{%0,%1,%2,%3}, {%4,%5,%6,%7}, {%8,%9}, {%0,%1,%2,%3};"
        : "+f"(c[0]), "+f"(c[1]), "+f"(c[2]), "+f"(c[3])
        : "r"(a[0]), "r"(a[1]), "r"(a[2]), "r"(a[3]), "r"(b0), "r"(b1));
}
__device__ __forceinline__ void cp16(uint32_t dst, const void* src) {
    asm volatile("cp.async.cg.shared.global [%0], [%1], 16;" :: "r"(dst), "l"(src));
}
__device__ __forceinline__ void cp_commit() {
    asm volatile("cp.async.commit_group;");
}
template <int N> __device__ __forceinline__ void cp_wait() {
    asm volatile("cp.async.wait_group %0;" :: "n"(N));
}
__device__ __forceinline__ void split2(float x, float y, uint32_t& hi, uint32_t& lo) {
    __nv_bfloat162 h = __floats2bfloat162_rn(x, y);
    __nv_bfloat162 l = __floats2bfloat162_rn(x - __bfloat162float(h.x),
                                             y - __bfloat162float(h.y));
    hi = *(uint32_t*)&h;
    lo = *(uint32_t*)&l;
}

// ---------------------------------------------------------------------------
// HMMA NT GEMM on pre-split bf16 hi/lo operands (3 MMAs per product).
// C[M,N] = A[M,K] @ B[N,K]^T (+bias)(relu).
// CTA tile 128x128, K staged 32, cp.async 3-stage pipeline.
// ---------------------------------------------------------------------------
#define STAGES 3
#define STAGE_BYTES 32768
#define SMEM_DYN (STAGES * STAGE_BYTES)   // 98304

template <bool HAS_BIAS, bool RELU, bool F32OUT>
__global__ __launch_bounds__(256, 2)
void hmma_gemm(const uint8_t* __restrict__ A, const uint8_t* __restrict__ B,
               const float* __restrict__ bias, float* __restrict__ Cf,
               uint8_t* __restrict__ Cs,
               int K, long long ldaB, long long ldbB, long long ldcB,
               long long sA, long long sB, long long sC)
{
    extern __shared__ uint8_t sm[];
    const long long bz = blockIdx.z;
    A += bz * sA;
    B += bz * sB;

    const int tid = threadIdx.x;
    const int wid = tid >> 5;
    const int lane = tid & 31;
    const int wm = wid & 3;
    const int wn = wid >> 2;
    const int lr = lane & 15;
    const int lc = lane >> 4;

    const int m0 = blockIdx.y * 128;
    const int n0 = blockIdx.x * 128;

    const int lrow = tid >> 1;          // 0..127
    const int cb = (tid & 1) * 4;       // chunk base 0 or 4
    const int rsw = lrow & 7;

    const uint32_t smb = smem_u32(sm);
    const uint8_t* srcA0 = A + (long long)(m0 + lrow) * ldaB + cb * 16;
    const uint8_t* srcB0 = B + (long long)(n0 + lrow) * ldbB + cb * 16;

    float acc[2][8][4];
#pragma unroll
    for (int i = 0; i < 2; ++i)
#pragma unroll
        for (int j = 0; j < 8; ++j)
#pragma unroll
            for (int t = 0; t < 4; ++t) acc[i][j][t] = 0.0f;

    const int S = K / 32;

#define ISSUE_STAGE(s)                                                        \
    do {                                                                      \
        const uint32_t dra = smb + ((s) % STAGES) * STAGE_BYTES + lrow * 128; \
        const uint8_t* pa = srcA0 + (s) * 128;                                \
        const uint8_t* pb = srcB0 + (s) * 128;                                \
        _Pragma("unroll")                                                     \
        for (int c = 0; c < 4; ++c)                                           \
            cp16(dra + (((cb + c) ^ rsw) << 4), pa + c * 16);                 \
        _Pragma("unroll")                                                     \
        for (int c = 0; c < 4; ++c)                                           \
            cp16(dra + 16384 + (((cb + c) ^ rsw) << 4), pb + c * 16);         \
        cp_commit();                                                          \
    } while (0)

    ISSUE_STAGE(0);
    ISSUE_STAGE(1);

    for (int s = 0; s < S; ++s) {
        if (s + 1 < S) cp_wait<1>(); else cp_wait<0>();
        __syncthreads();
        if (s + 2 < S) ISSUE_STAGE(s + 2);

        const uint32_t bufA = smb + (s % STAGES) * STAGE_BYTES;
        const uint32_t bufB = bufA + 16384;

#pragma unroll
        for (int kk = 0; kk < 2; ++kk) {
            uint32_t aH[2][4], aL[2][4];
#pragma unroll
            for (int mi = 0; mi < 2; ++mi) {
                const int r = wm * 32 + mi * 16 + lr;
                const int byteh = kk * 32 + lc * 16;
                const uint32_t rb = bufA + r * 128;
                const int rs = r & 7;
                ldsm4(aH[mi], rb + ((((byteh) >> 4) ^ rs) << 4));
                ldsm4(aL[mi], rb + ((((byteh + 64) >> 4) ^ rs) << 4));
            }
#pragma unroll
            for (int g = 0; g < 4; ++g) {
                const int r = wn * 64 + g * 16 + lr;
                const int byteh = kk * 32 + lc * 16;
                const uint32_t rb = bufB + r * 128;
                const int rs = r & 7;
                uint32_t bh[4], bl[4];
                ldsm4(bh, rb + ((((byteh) >> 4) ^ rs) << 4));
                ldsm4(bl, rb + ((((byteh + 64) >> 4) ^ rs) << 4));
#pragma unroll
                for (int mi = 0; mi < 2; ++mi) {
                    mma_bf16(acc[mi][2 * g],     aH[mi], bh[0], bh[2]);
                    mma_bf16(acc[mi][2 * g],     aH[mi], bl[0], bl[2]);
                    mma_bf16(acc[mi][2 * g],     aL[mi], bh[0], bh[2]);
                    mma_bf16(acc[mi][2 * g + 1], aH[mi], bh[1], bh[3]);
                    mma_bf16(acc[mi][2 * g + 1], aH[mi], bl[1], bl[3]);
                    mma_bf16(acc[mi][2 * g + 1], aL[mi], bh[1], bh[3]);
                }
            }
        }
    }
#undef ISSUE_STAGE

    // ---- epilogue ----
#pragma unroll
    for (int mi = 0; mi < 2; ++mi) {
        const long long r0 = m0 + wm * 32 + mi * 16 + (lane >> 2);
#pragma unroll
        for (int nj = 0; nj < 8; ++nj) {
            const int col = n0 + wn * 64 + nj * 8 + 2 * (lane & 3);
            float bx = 0.0f, by = 0.0f;
            if (HAS_BIAS) {
                const float2 bvv = *(const float2*)(bias + col);
                bx = bvv.x; by = bvv.y;
            }
            float x0 = acc[mi][nj][0] + bx;
            float x1 = acc[mi][nj][1] + by;
            float x2 = acc[mi][nj][2] + bx;
            float x3 = acc[mi][nj][3] + by;
            if (RELU) {
                x0 = fmaxf(x0, 0.0f); x1 = fmaxf(x1, 0.0f);
                x2 = fmaxf(x2, 0.0f); x3 = fmaxf(x3, 0.0f);
            }
            if (F32OUT) {
                uint8_t* base = (uint8_t*)Cf + bz * sC;
                *(float2*)(base + r0 * ldcB + col * 4)       = make_float2(x0, x1);
                *(float2*)(base + (r0 + 8) * ldcB + col * 4) = make_float2(x2, x3);
            } else {
                uint8_t* base = Cs + bz * sC;
                const long long cb0 = (long long)(col >> 5) * 128 + (col & 31) * 2;
                uint32_t hi, lo;
                split2(x0, x1, hi, lo);
                uint8_t* p = base + r0 * ldcB + cb0;
                *(uint32_t*)p = hi;
                *(uint32_t*)(p + 64) = lo;
                split2(x2, x3, hi, lo);
                p = base + (r0 + 8) * ldcB + cb0;
                *(uint32_t*)p = hi;
                *(uint32_t*)(p + 64) = lo;
            }
        }
    }
}

// ---------------------------------------------------------------------------
// AV GEMM: o[b] = att[b] @ vt[b]^T.  att fp16 single (2 MMAs), v fp16 hi/lo.
// A: fp16 plain [2048 x 2048], ldaB = 4096. B: fp16 split [512 x 2048], ldbB=8192.
// C: o split bf16, ldcB = 2048. K = 2048.
// ---------------------------------------------------------------------------
__global__ __launch_bounds__(256, 2)
void hmma_av(const uint8_t* __restrict__ A, const uint8_t* __restrict__ B,
             uint8_t* __restrict__ Cs)
{
    extern __shared__ uint8_t sm[];
    const long long bz = blockIdx.z;
    A += bz * (long long)NSEQ * 4096;
    B += bz * 512LL * 8192;

    const int tid = threadIdx.x;
    const int wid = tid >> 5;
    const int lane = tid & 31;
    const int wm = wid & 3;
    const int wn = wid >> 2;
    const int lr = lane & 15;
    const int lc = lane >> 4;

    const int m0 = blockIdx.y * 128;
    const int n0 = blockIdx.x * 128;

    const int lrow = tid >> 1;
    const int cbA = (tid & 1) * 2;      // A chunks 0..3 (64B of data per row)
    const int cbB = (tid & 1) * 4;      // B chunks 0..7
    const int rsw = lrow & 7;

    const uint32_t smb = smem_u32(sm);
    const uint8_t* srcA0 = A + (long long)(m0 + lrow) * 4096 + cbA * 16;
    const uint8_t* srcB0 = B + (long long)(n0 + lrow) * 8192 + cbB * 16;

    float acc[2][8][4];
#pragma unroll
    for (int i = 0; i < 2; ++i)
#pragma unroll
        for (int j = 0; j < 8; ++j)
#pragma unroll
            for (int t = 0; t < 4; ++t) acc[i][j][t] = 0.0f;

    const int S = NSEQ / 32;   // 64

#define ISSUE_AV(s)                                                           \
    do {                                                                      \
        const uint32_t dra = smb + ((s) % STAGES) * STAGE_BYTES + lrow * 128; \
        const uint8_t* pa = srcA0 + (s) * 64;                                 \
        const uint8_t* pb = srcB0 + (s) * 128;                                \
        _Pragma("unroll")                                                     \
        for (int c = 0; c < 2; ++c)                                           \
            cp16(dra + (((cbA + c) ^ rsw) << 4), pa + c * 16);                \
        _Pragma("unroll")                                                     \
        for (int c = 0; c < 4; ++c)                                           \
            cp16(dra + 16384 + (((cbB + c) ^ rsw) << 4), pb + c * 16);        \
        cp_commit();                                                          \
    } while (0)

    ISSUE_AV(0);
    ISSUE_AV(1);

    for (int s = 0; s < S; ++s) {
        if (s + 1 < S) cp_wait<1>(); else cp_wait<0>();
        __syncthreads();
        if (s + 2 < S) ISSUE_AV(s + 2);

        const uint32_t bufA = smb + (s % STAGES) * STAGE_BYTES;
        const uint32_t bufB = bufA + 16384;

#pragma unroll
        for (int kk = 0; kk < 2; ++kk) {
            uint32_t aF[2][4];
#pragma unroll
            for (int mi = 0; mi < 2; ++mi) {
                const int r = wm * 32 + mi * 16 + lr;
                const int chunk = kk * 2 + lc;
                ldsm4(aF[mi], bufA + r * 128 + (((chunk) ^ (r & 7)) << 4));
            }
#pragma unroll
            for (int g = 0; g < 4; ++g) {
                const int r = wn * 64 + g * 16 + lr;
                const int byteh = kk * 32 + lc * 16;
                const uint32_t rb = bufB + r * 128;
                const int rs = r & 7;
                uint32_t bh[4], bl[4];
                ldsm4(bh, rb + ((((byteh) >> 4) ^ rs) << 4));
                ldsm4(bl, rb + ((((byteh + 64) >> 4) ^ rs) << 4));
#pragma unroll
                for (int mi = 0; mi < 2; ++mi) {
                    mma_f16(acc[mi][2 * g],     aF[mi], bh[0], bh[2]);
                    mma_f16(acc[mi][2 * g],     aF[mi], bl[0], bl[2]);
                    mma_f16(acc[mi][2 * g + 1], aF[mi], bh[1], bh[3]);
                    mma_f16(acc[mi][2 * g + 1], aF[mi], bl[1], bl[3]);
                }
            }
        }
    }
#undef ISSUE_AV

    // ---- epilogue: write o split bf16 ----
    uint8_t* base = Cs + bz * (long long)NSEQ * 2048;
#pragma unroll
    for (int mi = 0; mi < 2; ++mi) {
        const long long r0 = m0 + wm * 32 + mi * 16 + (lane >> 2);
#pragma unroll
        for (int nj = 0; nj < 8; ++nj) {
            const int col = n0 + wn * 64 + nj * 8 + 2 * (lane & 3);
            const long long cb0 = (long long)(col >> 5) * 128 + (col & 31) * 2;
            uint32_t hi, lo;
            split2(acc[mi][nj][0], acc[mi][nj][1], hi, lo);
            uint8_t* p = base + r0 * 2048 + cb0;
            *(uint32_t*)p = hi;
            *(uint32_t*)(p + 64) = lo;
            split2(acc[mi][nj][2], acc[mi][nj][3], hi, lo);
            p = base + (r0 + 8) * 2048 + cb0;
            *(uint32_t*)p = hi;
            *(uint32_t*)(p + 64) = lo;
        }
    }
}

// ---------------------------------------------------------------------------
// fp32 -> split bf16 (no transpose). Row length fixed 512. 8 elems/thread.
// ---------------------------------------------------------------------------
__global__ __launch_bounds__(256)
void split_rows512(const float* __restrict__ in, uint8_t* __restrict__ out)
{
    const long long i8 = ((long long)blockIdx.x * 256 + threadIdx.x) * 8;
    const long long row = i8 >> 9;
    const int col = (int)(i8 & 511);
    const float4 a = *(const float4*)(in + i8);
    const float4 b = *(const float4*)(in + i8 + 4);
    uint4 hi, lo;
    split2(a.x, a.y, hi.x, lo.x);
    split2(a.z, a.w, hi.y, lo.y);
    split2(b.x, b.y, hi.z, lo.z);
    split2(b.z, b.w, hi.w, lo.w);
    uint8_t* p = out + row * 2048 + (col >> 5) * 128 + (col & 31) * 2;
    *(uint4*)p = hi;
    *(uint4*)(p + 64) = lo;
}

// ---------------------------------------------------------------------------
// Weight transpose + split bf16.
// ---------------------------------------------------------------------------
__global__ __launch_bounds__(256)
void transpose_split_w(const float* __restrict__ in, uint8_t* __restrict__ out,
                       int R, int C, long long rowOff)
{
    __shared__ float t[32][33];
    const int c0 = blockIdx.x * 32;
    const int r0 = blockIdx.y * 32;
    const int x = threadIdx.x;
    const int y = threadIdx.y;
#pragma unroll
    for (int j = 0; j < 32; j += 8)
        t[y + j][x] = in[(long long)(r0 + y + j) * C + c0 + x];
    __syncthreads();
#pragma unroll
    for (int j = 0; j < 32; j += 8) {
        const float val = t[x][y + j];
        const long long row = rowOff + c0 + y + j;
        const int col = r0 + x;
        __nv_bfloat16 hi = __float2bfloat16(val);
        __nv_bfloat16 lo = __float2bfloat16(val - __bfloat162float(hi));
        uint8_t* p = out + row * ((long long)R * 4) + (col >> 5) * 128 + (col & 31) * 2;
        *(__nv_bfloat16*)p = hi;
        *(__nv_bfloat16*)(p + 64) = lo;
    }
}

// ---------------------------------------------------------------------------
// v^T: read v from qkv split bf16 (col offset 1024, row bytes 6144), write vt
// as fp16 hi/lo split, per batch [512 rows][2048 cols] (row bytes 8192).
// ---------------------------------------------------------------------------
__global__ __launch_bounds__(256)
void vt_transpose(const uint8_t* __restrict__ qkv, uint8_t* __restrict__ vt)
{
    __shared__ float t[32][33];
    const long long b = blockIdx.z;
    const int h0 = blockIdx.x * 32;
    const int n0 = blockIdx.y * 32;
    const int x = threadIdx.x;
    const int y = threadIdx.y;
#pragma unroll
    for (int j = 0; j < 32; j += 8) {
        const long long row = b * 2048 + n0 + y + j;
        const int col = 1024 + h0 + x;
        const uint8_t* p = qkv + row * 6144 + (col >> 5) * 128 + (col & 31) * 2;
        t[y + j][x] = __bfloat162float(*(const __nv_bfloat16*)p) +
                      __bfloat162float(*(const __nv_bfloat16*)(p + 64));
    }
    __syncthreads();
#pragma unroll
    for (int j = 0; j < 32; j += 8) {
        const float val = t[x][y + j];
        const long long row = h0 + y + j;
        const int col = n0 + x;
        __half hi = __float2half_rn(val);
        __half lo = __float2half_rn(val - __half2float(hi));
        uint8_t* p = vt + b * (512LL * 8192) + row * 8192 + (col >> 5) * 128 + (col & 31) * 2;
        *(__half*)p = hi;
        *(__half*)(p + 64) = lo;
    }
}

// ---------------------------------------------------------------------------
// Row softmax (2048) reading fp32, writing fp16 plain. One block per row.
// ---------------------------------------------------------------------------
__global__ __launch_bounds__(256)
void softmax_f16_kernel(const float* __restrict__ att, __half* __restrict__ outh)
{
    const float* row = att + (long long)blockIdx.x * NSEQ;
    __half* orow = outh + (long long)blockIdx.x * NSEQ;
    __shared__ float red[256];
    const int tid = threadIdx.x;
    const int c0 = tid * 8;

    float r[8];
    *(float4*)&r[0] = *(const float4*)(row + c0);
    *(float4*)&r[4] = *(const float4*)(row + c0 + 4);

    float m = r[0];
#pragma unroll
    for (int p = 1; p < 8; ++p) m = fmaxf(m, r[p]);
    red[tid] = m;
    __syncthreads();
#pragma unroll
    for (int s = 128; s > 0; s >>= 1) {
        if (tid < s) red[tid] = fmaxf(red[tid], red[tid + s]);
        __syncthreads();
    }
    m = red[0];
    __syncthreads();

    float sum = 0.0f;
#pragma unroll
    for (int p = 0; p < 8; ++p) {
        r[p] = __expf(r[p] - m);
        sum += r[p];
    }
    red[tid] = sum;
    __syncthreads();
#pragma unroll
    for (int s = 128; s > 0; s >>= 1) {
        if (tid < s) red[tid] += red[tid + s];
        __syncthreads();
    }
    const float inv = 1.0f / red[0];

    __half2 h[4];
#pragma unroll
    for (int p = 0; p < 4; ++p)
        h[p] = __floats2half2_rn(r[2 * p] * inv, r[2 * p + 1] * inv);
    *(uint4*)(orow + c0) = *(uint4*)h;
}

__global__ void concat_bias(const float* bq, const float* bk, const float* bv,
                            float* dst)
{
    const int t = blockIdx.x * 256 + threadIdx.x;
    if (t < 512) {
        dst[t] = bq[t];
        dst[512 + t] = bk[t];
        dst[1024 + t] = bv[t];
    }
}

// ---------------------------------------------------------------------------
// Launch
// ---------------------------------------------------------------------------
extern "C" void kernel_launch(void* const* d_in, const int* in_sizes, int n_in,
                              void* d_out, int out_size)
{
    (void)in_sizes; (void)n_in; (void)out_size;
    const float* h  = (const float*)d_in[1];
    const float* Wv = (const float*)d_in[2];
    const float* bv = (const float*)d_in[3];
    const float* Wk = (const float*)d_in[4];
    const float* bk = (const float*)d_in[5];
    const float* Wq = (const float*)d_in[6];
    const float* bq = (const float*)d_in[7];
    const float* W1 = (const float*)d_in[8];
    const float* b1 = (const float*)d_in[9];
    const float* W2 = (const float*)d_in[10];
    const float* b2 = (const float*)d_in[11];
    float* out = (float*)d_out;

    uint8_t *hs, *qkvs, *vts, *os, *hids, *ws;
    float *att, *bqkv;
    __half* atth;
    cudaGetSymbolAddress((void**)&hs,   g_h_s);
    cudaGetSymbolAddress((void**)&qkvs, g_qkv_s);
    cudaGetSymbolAddress((void**)&vts,  g_vt_s);
    cudaGetSymbolAddress((void**)&os,   g_o_s);
    cudaGetSymbolAddress((void**)&hids, g_hid_s);
    cudaGetSymbolAddress((void**)&ws,   g_w_s);
    cudaGetSymbolAddress((void**)&att,  g_att);
    cudaGetSymbolAddress((void**)&atth, g_atth);
    cudaGetSymbolAddress((void**)&bqkv, g_bqkv);

    cudaFuncSetAttribute(hmma_gemm<true,  false, false>, cudaFuncAttributeMaxDynamicSharedMemorySize, SMEM_DYN);
    cudaFuncSetAttribute(hmma_gemm<false, false, true >, cudaFuncAttributeMaxDynamicSharedMemorySize, SMEM_DYN);
    cudaFuncSetAttribute(hmma_gemm<true,  true,  false>, cudaFuncAttributeMaxDynamicSharedMemorySize, SMEM_DYN);
    cudaFuncSetAttribute(hmma_gemm<true,  false, true >, cudaFuncAttributeMaxDynamicSharedMemorySize, SMEM_DYN);
    cudaFuncSetAttribute(hmma_av, cudaFuncAttributeMaxDynamicSharedMemorySize, SMEM_DYN);

    uint8_t* wqkv = ws;                                  // 1536 rows x 2048B
    uint8_t* w1t  = ws + 1536LL * 2048;                  // 512 rows
    uint8_t* w2t  = ws + 2048LL * 2048;                  // 512 rows

    // 0) prep
    concat_bias<<<2, 256>>>(bq, bk, bv, bqkv);
    {
        dim3 blk(32, 8), grd(16, 16);
        transpose_split_w<<<grd, blk>>>(Wq, wqkv, 512, 512, 0);
        transpose_split_w<<<grd, blk>>>(Wk, wqkv, 512, 512, 512);
        transpose_split_w<<<grd, blk>>>(Wv, wqkv, 512, 512, 1024);
        transpose_split_w<<<grd, blk>>>(W1, w1t, 512, 512, 0);
        transpose_split_w<<<grd, blk>>>(W2, w2t, 512, 512, 0);
    }
    split_rows512<<<(BN_ROWS * 512 / 8) / 256, 256>>>(h, hs);

    // 1) fused QKV: [32768,1536] = h @ wqkv^T + bqkv -> qkv split (ldc 6144B)
    {
        dim3 grd(1536 / 128, BN_ROWS / 128, 1);
        hmma_gemm<true, false, false><<<grd, 256, SMEM_DYN>>>(
            hs, wqkv, bqkv, nullptr, qkvs, 512, 2048, 2048, 6144, 0, 0, 0);
    }

    // 2) v^T per batch -> fp16 split
    {
        dim3 blk(32, 8), grd(512 / 32, 2048 / 32, BB);
        vt_transpose<<<grd, blk>>>(qkvs, vts);
    }

    // 3) logits: att[b] = q @ k^T (fp32 out)
    {
        dim3 grd(NSEQ / 128, NSEQ / 128, BB);
        hmma_gemm<false, false, true><<<grd, 256, SMEM_DYN>>>(
            qkvs, qkvs + 2048, nullptr, att, nullptr,
            512, 6144, 6144, 8192,
            2048LL * 6144, 2048LL * 6144, 2048LL * 8192);
    }

    // 4) softmax -> att fp16
    softmax_f16_kernel<<<BN_ROWS, 256>>>(att, atth);

    // 5) o[b] = att @ vt^T (fp16, 2-MMA) -> o split bf16
    {
        dim3 grd(HH / 128, NSEQ / 128, BB);
        hmma_av<<<grd, 256, SMEM_DYN>>>((const uint8_t*)atth, vts, os);
    }

    // 6) hid = relu(o @ w1t^T + b1) -> hid split
    {
        dim3 grd(HH / 128, BN_ROWS / 128, 1);
        hmma_gemm<true, true, false><<<grd, 256, SMEM_DYN>>>(
            os, w1t, b1, nullptr, hids, 512, 2048, 2048, 2048, 0, 0, 0);
    }

    // 7) out = hid @ w2t^T + b2 (fp32 out)
    {
        dim3 grd(MM / 128, BN_ROWS / 128, 1);
        hmma_gemm<true, false, true><<<grd, 256, SMEM_DYN>>>(
            hids, w2t, b2, out, nullptr, 512, 2048, 2048, 2048, 0, 0, 0);
    }
}

// round 6
// speedup vs baseline: 2.9347x; 1.1815x over previous
#include <cuda_runtime.h>
#include <cuda_fp16.h>
#include <math.h>
#include <stdint.h>

// Problem dims (fixed)
#define BB 16
#define NSEQ 2048
#define MM 512
#define HH 512
#define BN_ROWS (BB * NSEQ)   // 32768

// ---------------------------------------------------------------------------
// Split layout (fp16): for a logical [R x K] matrix, 4 bytes/elem as groups of
// 32 columns: each 128B group = 32 fp16 "hi" then 32 fp16 "lo".
// byte(r, c) = r*rowBytes + (c>>5)*128 + (c&31)*2   (hi; lo at +64)
// Plain fp16 layout: byte(r, c) = r*rowBytes + c*2.
// ---------------------------------------------------------------------------
__device__ __align__(128) uint8_t g_h_s  [(long long)BN_ROWS * HH * 4];     // h split
__device__ __align__(128) uint8_t g_qk_s [(long long)BN_ROWS * 1024 * 4];   // q|k split
__device__ __align__(128) uint8_t g_v16  [(long long)BN_ROWS * HH * 2];     // v plain
__device__ __align__(128) uint8_t g_vt16 [(long long)BN_ROWS * HH * 2];     // v^T plain
__device__ __align__(128) uint8_t g_o_s  [(long long)BN_ROWS * HH * 4];     // o split
__device__ __align__(128) uint8_t g_hid_s[(long long)BN_ROWS * HH * 4];     // hid split
__device__ __align__(128) uint8_t g_wqk_s[1024LL * 512 * 4];                // Wq^T|Wk^T split
__device__ __align__(128) uint8_t g_wv16 [512LL * 512 * 2];                 // Wv^T plain
__device__ __align__(128) uint8_t g_w116 [512LL * 512 * 2];                 // W1^T plain
__device__ __align__(128) uint8_t g_w216 [512LL * 512 * 2];                 // W2^T plain
__device__ float g_att[(long long)BB * NSEQ * NSEQ];
__device__ __align__(128) __half g_atth[(long long)BB * NSEQ * NSEQ];
__device__ float g_bqk[1024];

// ---------------------------------------------------------------------------
// Helpers
// ---------------------------------------------------------------------------
__device__ __forceinline__ uint32_t smem_u32(const void* p) {
    uint32_t a;
    asm("{ .reg .u64 t; cvta.to.shared.u64 t, %1; cvt.u32.u64 %0, t; }" : "=r"(a) : "l"(p));
    return a;
}
__device__ __forceinline__ void ldsm4(uint32_t* r, uint32_t addr) {
    asm volatile("ldmatrix.sync.aligned.m8n8.x4.shared.b16 {%0,%1,%2,%3}, [%4];"
                 : "=r"(r[0]), "=r"(r[1]), "=r"(r[2]), "=r"(r[3]) : "r"(addr));
}
__device__ __forceinline__ void mma_f16(float* c, const uint32_t* a,
                                        uint32_t b0, uint32_t b1) {
    asm volatile(
        "mma.sync.aligned.m16n8k16.row.col.f32.f16.f16.f32 "
        "{%0,%1,%2,%3}, {%4,%5,%6,%7}, {%8,%9}, {%0,%1,%2,%3};"
        : "+f"(c[0]), "+f"(c[1]), "+f"(c[2]), "+f"(c[3])
        : "r"(a[0]), "r"(a[1]), "r"(a[2]), "r"(a[3]), "r"(b0), "r"(b1));
}
__device__ __forceinline__ void cp16(uint32_t dst, const void* src) {
    asm volatile("cp.async.cg.shared.global [%0], [%1], 16;" :: "r"(dst), "l"(src));
}
__device__ __forceinline__ void cp_commit() {
    asm volatile("cp.async.commit_group;");
}
template <int N> __device__ __forceinline__ void cp_wait() {
    asm volatile("cp.async.wait_group %0;" :: "n"(N));
}
__device__ __forceinline__ void split2h(float x, float y, uint32_t& hi, uint32_t& lo) {
    __half2 h = __floats2half2_rn(x, y);
    __half2 l = __floats2half2_rn(x - __half2float(h.x), y - __half2float(h.y));
    hi = *(uint32_t*)&h;
    lo = *(uint32_t*)&l;
}

// Plain-fp16 smem tile addressing (64B of data per row, 2 rows packed per 128B
// line, 8-chunk XOR swizzle): conflict-free for ldmatrix and cp.async.
__device__ __forceinline__ uint32_t plainb_addr(uint32_t base, int r, int c) {
    return base + ((r >> 1) << 7) + (((((r & 1) << 2) + c) ^ ((r >> 1) & 7)) << 4);
}

// OUTMODE: 0 = fp32, 1 = split fp16, 2 = plain fp16
#define STAGES 3

// ---------------------------------------------------------------------------
// gemm3: A split fp16, B split fp16, 3 MMAs (HH, HL, LH).
// C[M,N] = A[M,K] @ B[N,K]^T (+bias). CTA 128x128, K staged 32, 3-deep cp.async.
// stage = A 16KB + B 16KB.
// ---------------------------------------------------------------------------
#define G3_STAGE 32768
#define G3_SMEM (STAGES * G3_STAGE)

template <bool HAS_BIAS, int OUTMODE>
__global__ __launch_bounds__(256, 2)
void hmma_gemm3(const uint8_t* __restrict__ A, const uint8_t* __restrict__ B,
                const float* __restrict__ bias, float* __restrict__ Cf,
                uint8_t* __restrict__ Cs,
                int K, long long ldaB, long long ldbB, long long ldcB,
                long long sA, long long sB, long long sC)
{
    extern __shared__ uint8_t sm[];
    const long long bz = blockIdx.z;
    A += bz * sA;
    B += bz * sB;

    const int tid = threadIdx.x;
    const int wid = tid >> 5, lane = tid & 31;
    const int wm = wid & 3, wn = wid >> 2;
    const int lr = lane & 15, lc = lane >> 4;
    const int m0 = blockIdx.y * 128, n0 = blockIdx.x * 128;

    const int lrow = tid >> 1;
    const int cb = (tid & 1) * 4;
    const int rsw = lrow & 7;

    const uint32_t smb = smem_u32(sm);
    const uint8_t* srcA0 = A + (long long)(m0 + lrow) * ldaB + cb * 16;
    const uint8_t* srcB0 = B + (long long)(n0 + lrow) * ldbB + cb * 16;

    float acc[2][8][4];
#pragma unroll
    for (int i = 0; i < 2; ++i)
#pragma unroll
        for (int j = 0; j < 8; ++j)
#pragma unroll
            for (int t = 0; t < 4; ++t) acc[i][j][t] = 0.0f;

    const int S = K / 32;

#define G3_ISSUE(s)                                                           \
    do {                                                                      \
        const uint32_t dra = smb + ((s) % STAGES) * G3_STAGE + lrow * 128;    \
        const uint8_t* pa = srcA0 + (s) * 128;                                \
        const uint8_t* pb = srcB0 + (s) * 128;                                \
        _Pragma("unroll")                                                     \
        for (int c = 0; c < 4; ++c)                                           \
            cp16(dra + (((cb + c) ^ rsw) << 4), pa + c * 16);                 \
        _Pragma("unroll")                                                     \
        for (int c = 0; c < 4; ++c)                                           \
            cp16(dra + 16384 + (((cb + c) ^ rsw) << 4), pb + c * 16);         \
        cp_commit();                                                          \
    } while (0)

    G3_ISSUE(0);
    G3_ISSUE(1);

    for (int s = 0; s < S; ++s) {
        if (s + 1 < S) cp_wait<1>(); else cp_wait<0>();
        __syncthreads();
        if (s + 2 < S) G3_ISSUE(s + 2);

        const uint32_t bufA = smb + (s % STAGES) * G3_STAGE;
        const uint32_t bufB = bufA + 16384;

#pragma unroll
        for (int kk = 0; kk < 2; ++kk) {
            uint32_t aH[2][4], aL[2][4];
#pragma unroll
            for (int mi = 0; mi < 2; ++mi) {
                const int r = wm * 32 + mi * 16 + lr;
                const int byteh = kk * 32 + lc * 16;
                const uint32_t rb = bufA + r * 128;
                const int rs = r & 7;
                ldsm4(aH[mi], rb + ((((byteh) >> 4) ^ rs) << 4));
                ldsm4(aL[mi], rb + ((((byteh + 64) >> 4) ^ rs) << 4));
            }
#pragma unroll
            for (int g = 0; g < 4; ++g) {
                const int r = wn * 64 + g * 16 + lr;
                const int byteh = kk * 32 + lc * 16;
                const uint32_t rb = bufB + r * 128;
                const int rs = r & 7;
                uint32_t bh[4], bl[4];
                ldsm4(bh, rb + ((((byteh) >> 4) ^ rs) << 4));
                ldsm4(bl, rb + ((((byteh + 64) >> 4) ^ rs) << 4));
#pragma unroll
                for (int mi = 0; mi < 2; ++mi) {
                    mma_f16(acc[mi][2 * g],     aH[mi], bh[0], bh[2]);
                    mma_f16(acc[mi][2 * g],     aH[mi], bl[0], bl[2]);
                    mma_f16(acc[mi][2 * g],     aL[mi], bh[0], bh[2]);
                    mma_f16(acc[mi][2 * g + 1], aH[mi], bh[1], bh[3]);
                    mma_f16(acc[mi][2 * g + 1], aH[mi], bl[1], bl[3]);
                    mma_f16(acc[mi][2 * g + 1], aL[mi], bh[1], bh[3]);
                }
            }
        }
    }
#undef G3_ISSUE

#pragma unroll
    for (int mi = 0; mi < 2; ++mi) {
        const long long r0 = m0 + wm * 32 + mi * 16 + (lane >> 2);
#pragma unroll
        for (int nj = 0; nj < 8; ++nj) {
            const int col = n0 + wn * 64 + nj * 8 + 2 * (lane & 3);
            float bx = 0.0f, by = 0.0f;
            if (HAS_BIAS) {
                const float2 bvv = *(const float2*)(bias + col);
                bx = bvv.x; by = bvv.y;
            }
            const float x0 = acc[mi][nj][0] + bx;
            const float x1 = acc[mi][nj][1] + by;
            const float x2 = acc[mi][nj][2] + bx;
            const float x3 = acc[mi][nj][3] + by;
            if (OUTMODE == 0) {
                uint8_t* base = (uint8_t*)Cf + bz * sC;
                *(float2*)(base + r0 * ldcB + col * 4)       = make_float2(x0, x1);
                *(float2*)(base + (r0 + 8) * ldcB + col * 4) = make_float2(x2, x3);
            } else {
                uint8_t* base = Cs + bz * sC;
                const long long cb0 = (long long)(col >> 5) * 128 + (col & 31) * 2;
                uint32_t hi, lo;
                split2h(x0, x1, hi, lo);
                uint8_t* p = base + r0 * ldcB + cb0;
                *(uint32_t*)p = hi;
                *(uint32_t*)(p + 64) = lo;
                split2h(x2, x3, hi, lo);
                p = base + (r0 + 8) * ldcB + cb0;
                *(uint32_t*)p = hi;
                *(uint32_t*)(p + 64) = lo;
            }
        }
    }
}

// ---------------------------------------------------------------------------
// gemm2: A split fp16, B plain fp16 (single), 2 MMAs (aH*b + aL*b).
// stage = A 16KB + B 8KB = 24KB.
// ---------------------------------------------------------------------------
#define G2_STAGE 24576
#define G2_SMEM (STAGES * G2_STAGE)

template <bool HAS_BIAS, bool RELU, int OUTMODE>
__global__ __launch_bounds__(256, 2)
void hmma_gemm2(const uint8_t* __restrict__ A, const uint8_t* __restrict__ B,
                const float* __restrict__ bias, float* __restrict__ Cf,
                uint8_t* __restrict__ Cs,
                int K, long long ldaB, long long ldbB, long long ldcB)
{
    extern __shared__ uint8_t sm[];
    const int tid = threadIdx.x;
    const int wid = tid >> 5, lane = tid & 31;
    const int wm = wid & 3, wn = wid >> 2;
    const int lr = lane & 15, lc = lane >> 4;
    const int m0 = blockIdx.y * 128, n0 = blockIdx.x * 128;

    const int lrow = tid >> 1;
    const int cbA = (tid & 1) * 4;
    const int cbB = (tid & 1) * 2;
    const int rsw = lrow & 7;

    const uint32_t smb = smem_u32(sm);
    const uint8_t* srcA0 = A + (long long)(m0 + lrow) * ldaB + cbA * 16;
    const uint8_t* srcB0 = B + (long long)(n0 + lrow) * ldbB + cbB * 16;

    float acc[2][8][4];
#pragma unroll
    for (int i = 0; i < 2; ++i)
#pragma unroll
        for (int j = 0; j < 8; ++j)
#pragma unroll
            for (int t = 0; t < 4; ++t) acc[i][j][t] = 0.0f;

    const int S = K / 32;

#define G2_ISSUE(s)                                                           \
    do {                                                                      \
        const uint32_t stb = smb + ((s) % STAGES) * G2_STAGE;                 \
        const uint8_t* pa = srcA0 + (s) * 128;                                \
        const uint8_t* pb = srcB0 + (s) * 64;                                 \
        const uint32_t dra = stb + lrow * 128;                                \
        _Pragma("unroll")                                                     \
        for (int c = 0; c < 4; ++c)                                           \
            cp16(dra + (((cbA + c) ^ rsw) << 4), pa + c * 16);                \
        _Pragma("unroll")                                                     \
        for (int c = 0; c < 2; ++c)                                           \
            cp16(plainb_addr(stb + 16384, lrow, cbB + c), pb + c * 16);       \
        cp_commit();                                                          \
    } while (0)

    G2_ISSUE(0);
    G2_ISSUE(1);

    for (int s = 0; s < S; ++s) {
        if (s + 1 < S) cp_wait<1>(); else cp_wait<0>();
        __syncthreads();
        if (s + 2 < S) G2_ISSUE(s + 2);

        const uint32_t bufA = smb + (s % STAGES) * G2_STAGE;
        const uint32_t bufB = bufA + 16384;

#pragma unroll
        for (int kk = 0; kk < 2; ++kk) {
            uint32_t aH[2][4], aL[2][4];
#pragma unroll
            for (int mi = 0; mi < 2; ++mi) {
                const int r = wm * 32 + mi * 16 + lr;
                const int byteh = kk * 32 + lc * 16;
                const uint32_t rb = bufA + r * 128;
                const int rs = r & 7;
                ldsm4(aH[mi], rb + ((((byteh) >> 4) ^ rs) << 4));
                ldsm4(aL[mi], rb + ((((byteh + 64) >> 4) ^ rs) << 4));
            }
#pragma unroll
            for (int g = 0; g < 4; ++g) {
                const int r = wn * 64 + g * 16 + lr;
                const int c = kk * 2 + lc;
                uint32_t b[4];
                ldsm4(b, plainb_addr(bufB, r, c));
#pragma unroll
                for (int mi = 0; mi < 2; ++mi) {
                    mma_f16(acc[mi][2 * g],     aH[mi], b[0], b[2]);
                    mma_f16(acc[mi][2 * g],     aL[mi], b[0], b[2]);
                    mma_f16(acc[mi][2 * g + 1], aH[mi], b[1], b[3]);
                    mma_f16(acc[mi][2 * g + 1], aL[mi], b[1], b[3]);
                }
            }
        }
    }
#undef G2_ISSUE

#pragma unroll
    for (int mi = 0; mi < 2; ++mi) {
        const long long r0 = m0 + wm * 32 + mi * 16 + (lane >> 2);
#pragma unroll
        for (int nj = 0; nj < 8; ++nj) {
            const int col = n0 + wn * 64 + nj * 8 + 2 * (lane & 3);
            float bx = 0.0f, by = 0.0f;
            if (HAS_BIAS) {
                const float2 bvv = *(const float2*)(bias + col);
                bx = bvv.x; by = bvv.y;
            }
            float x0 = acc[mi][nj][0] + bx;
            float x1 = acc[mi][nj][1] + by;
            float x2 = acc[mi][nj][2] + bx;
            float x3 = acc[mi][nj][3] + by;
            if (RELU) {
                x0 = fmaxf(x0, 0.0f); x1 = fmaxf(x1, 0.0f);
                x2 = fmaxf(x2, 0.0f); x3 = fmaxf(x3, 0.0f);
            }
            if (OUTMODE == 0) {
                *(float2*)((uint8_t*)Cf + r0 * ldcB + col * 4)       = make_float2(x0, x1);
                *(float2*)((uint8_t*)Cf + (r0 + 8) * ldcB + col * 4) = make_float2(x2, x3);
            } else if (OUTMODE == 1) {
                const long long cb0 = (long long)(col >> 5) * 128 + (col & 31) * 2;
                uint32_t hi, lo;
                split2h(x0, x1, hi, lo);
                uint8_t* p = Cs + r0 * ldcB + cb0;
                *(uint32_t*)p = hi;
                *(uint32_t*)(p + 64) = lo;
                split2h(x2, x3, hi, lo);
                p = Cs + (r0 + 8) * ldcB + cb0;
                *(uint32_t*)p = hi;
                *(uint32_t*)(p + 64) = lo;
            } else {
                __half2 v01 = __floats2half2_rn(x0, x1);
                __half2 v23 = __floats2half2_rn(x2, x3);
                *(uint32_t*)(Cs + r0 * ldcB + col * 2)       = *(uint32_t*)&v01;
                *(uint32_t*)(Cs + (r0 + 8) * ldcB + col * 2) = *(uint32_t*)&v23;
            }
        }
    }
}

// ---------------------------------------------------------------------------
// av1: o[b] = att[b] @ vt[b]^T; both plain fp16, 1 MMA. Out: o split fp16.
// stage = A 8KB + B 8KB = 16KB.
// ---------------------------------------------------------------------------
#define AV_STAGE 16384
#define AV_SMEM (STAGES * AV_STAGE)

__global__ __launch_bounds__(256, 2)
void hmma_av1(const uint8_t* __restrict__ A, const uint8_t* __restrict__ B,
              uint8_t* __restrict__ Cs)
{
    extern __shared__ uint8_t sm[];
    const long long bz = blockIdx.z;
    A += bz * (long long)NSEQ * 4096;       // att rows, 2048 fp16
    B += bz * 512LL * 4096;                 // vt rows, 2048 fp16

    const int tid = threadIdx.x;
    const int wid = tid >> 5, lane = tid & 31;
    const int wm = wid & 3, wn = wid >> 2;
    const int lr = lane & 15, lc = lane >> 4;
    const int m0 = blockIdx.y * 128, n0 = blockIdx.x * 128;

    const int lrow = tid >> 1;
    const int cb2 = (tid & 1) * 2;

    const uint32_t smb = smem_u32(sm);
    const uint8_t* srcA0 = A + (long long)(m0 + lrow) * 4096 + cb2 * 16;
    const uint8_t* srcB0 = B + (long long)(n0 + lrow) * 4096 + cb2 * 16;

    float acc[2][8][4];
#pragma unroll
    for (int i = 0; i < 2; ++i)
#pragma unroll
        for (int j = 0; j < 8; ++j)
#pragma unroll
            for (int t = 0; t < 4; ++t) acc[i][j][t] = 0.0f;

    const int S = NSEQ / 32;  // 64

#define AV_ISSUE(s)                                                           \
    do {                                                                      \
        const uint32_t stb = smb + ((s) % STAGES) * AV_STAGE;                 \
        const uint8_t* pa = srcA0 + (s) * 64;                                 \
        const uint8_t* pb = srcB0 + (s) * 64;                                 \
        _Pragma("unroll")                                                     \
        for (int c = 0; c < 2; ++c)                                           \
            cp16(plainb_addr(stb, lrow, cb2 + c), pa + c * 16);               \
        _Pragma("unroll")                                                     \
        for (int c = 0; c < 2; ++c)                                           \
            cp16(plainb_addr(stb + 8192, lrow, cb2 + c), pb + c * 16);        \
        cp_commit();                                                          \
    } while (0)

    AV_ISSUE(0);
    AV_ISSUE(1);

    for (int s = 0; s < S; ++s) {
        if (s + 1 < S) cp_wait<1>(); else cp_wait<0>();
        __syncthreads();
        if (s + 2 < S) AV_ISSUE(s + 2);

        const uint32_t bufA = smb + (s % STAGES) * AV_STAGE;
        const uint32_t bufB = bufA + 8192;

#pragma unroll
        for (int kk = 0; kk < 2; ++kk) {
            const int c = kk * 2 + lc;
            uint32_t aF[2][4];
#pragma unroll
            for (int mi = 0; mi < 2; ++mi) {
                const int r = wm * 32 + mi * 16 + lr;
                ldsm4(aF[mi], plainb_addr(bufA, r, c));
            }
#pragma unroll
            for (int g = 0; g < 4; ++g) {
                const int r = wn * 64 + g * 16 + lr;
                uint32_t b[4];
                ldsm4(b, plainb_addr(bufB, r, c));
#pragma unroll
                for (int mi = 0; mi < 2; ++mi) {
                    mma_f16(acc[mi][2 * g],     aF[mi], b[0], b[2]);
                    mma_f16(acc[mi][2 * g + 1], aF[mi], b[1], b[3]);
                }
            }
        }
    }
#undef AV_ISSUE

    // epilogue: o split fp16, global rows
#pragma unroll
    for (int mi = 0; mi < 2; ++mi) {
        const long long r0 = bz * NSEQ + m0 + wm * 32 + mi * 16 + (lane >> 2);
#pragma unroll
        for (int nj = 0; nj < 8; ++nj) {
            const int col = n0 + wn * 64 + nj * 8 + 2 * (lane & 3);
            const long long cb0 = (long long)(col >> 5) * 128 + (col & 31) * 2;
            uint32_t hi, lo;
            split2h(acc[mi][nj][0], acc[mi][nj][1], hi, lo);
            uint8_t* p = Cs + r0 * 2048 + cb0;
            *(uint32_t*)p = hi;
            *(uint32_t*)(p + 64) = lo;
            split2h(acc[mi][nj][2], acc[mi][nj][3], hi, lo);
            p = Cs + (r0 + 8) * 2048 + cb0;
            *(uint32_t*)p = hi;
            *(uint32_t*)(p + 64) = lo;
        }
    }
}

// ---------------------------------------------------------------------------
// Prep kernels
// ---------------------------------------------------------------------------
__global__ __launch_bounds__(256)
void split16_rows512(const float* __restrict__ in, uint8_t* __restrict__ out)
{
    const long long i8 = ((long long)blockIdx.x * 256 + threadIdx.x) * 8;
    const long long row = i8 >> 9;
    const int col = (int)(i8 & 511);
    const float4 a = *(const float4*)(in + i8);
    const float4 b = *(const float4*)(in + i8 + 4);
    uint4 hi, lo;
    split2h(a.x, a.y, hi.x, lo.x);
    split2h(a.z, a.w, hi.y, lo.y);
    split2h(b.x, b.y, hi.z, lo.z);
    split2h(b.z, b.w, hi.w, lo.w);
    uint8_t* p = out + row * 2048 + (col >> 5) * 128 + (col & 31) * 2;
    *(uint4*)p = hi;
    *(uint4*)(p + 64) = lo;
}

__global__ __launch_bounds__(256)
void transpose_split_w16(const float* __restrict__ in, uint8_t* __restrict__ out,
                         long long rowOff)
{
    __shared__ float t[32][33];
    const int c0 = blockIdx.x * 32;
    const int r0 = blockIdx.y * 32;
    const int x = threadIdx.x;
    const int y = threadIdx.y;
#pragma unroll
    for (int j = 0; j < 32; j += 8)
        t[y + j][x] = in[(long long)(r0 + y + j) * 512 + c0 + x];
    __syncthreads();
#pragma unroll
    for (int j = 0; j < 32; j += 8) {
        const float val = t[x][y + j];
        const long long row = rowOff + c0 + y + j;
        const int col = r0 + x;
        __half hi = __float2half_rn(val);
        __half lo = __float2half_rn(val - __half2float(hi));
        uint8_t* p = out + row * 2048 + (col >> 5) * 128 + (col & 31) * 2;
        *(__half*)p = hi;
        *(__half*)(p + 64) = lo;
    }
}

__global__ __launch_bounds__(256)
void transpose_plain_w16(const float* __restrict__ in, __half* __restrict__ out)
{
    __shared__ float t[32][33];
    const int c0 = blockIdx.x * 32;
    const int r0 = blockIdx.y * 32;
    const int x = threadIdx.x;
    const int y = threadIdx.y;
#pragma unroll
    for (int j = 0; j < 32; j += 8)
        t[y + j][x] = in[(long long)(r0 + y + j) * 512 + c0 + x];
    __syncthreads();
#pragma unroll
    for (int j = 0; j < 32; j += 8)
        out[(long long)(c0 + y + j) * 512 + r0 + x] = __float2half_rn(t[x][y + j]);
}

__global__ __launch_bounds__(256)
void vt_transpose16(const __half* __restrict__ v, __half* __restrict__ vt)
{
    __shared__ __half t[32][33];
    const long long b = blockIdx.z;
    const int h0 = blockIdx.x * 32;
    const int n0 = blockIdx.y * 32;
    const int x = threadIdx.x;
    const int y = threadIdx.y;
#pragma unroll
    for (int j = 0; j < 32; j += 8)
        t[y + j][x] = v[(b * 2048 + n0 + y + j) * 512 + h0 + x];
    __syncthreads();
#pragma unroll
    for (int j = 0; j < 32; j += 8)
        vt[b * 512 * 2048 + (long long)(h0 + y + j) * 2048 + n0 + x] = t[x][y + j];
}

__global__ __launch_bounds__(256)
void softmax_f16_kernel(const float* __restrict__ att, __half* __restrict__ outh)
{
    const float* row = att + (long long)blockIdx.x * NSEQ;
    __half* orow = outh + (long long)blockIdx.x * NSEQ;
    __shared__ float red[256];
    const int tid = threadIdx.x;
    const int c0 = tid * 8;

    float r[8];
    *(float4*)&r[0] = *(const float4*)(row + c0);
    *(float4*)&r[4] = *(const float4*)(row + c0 + 4);

    float m = r[0];
#pragma unroll
    for (int p = 1; p < 8; ++p) m = fmaxf(m, r[p]);
    red[tid] = m;
    __syncthreads();
#pragma unroll
    for (int s = 128; s > 0; s >>= 1) {
        if (tid < s) red[tid] = fmaxf(red[tid], red[tid + s]);
        __syncthreads();
    }
    m = red[0];
    __syncthreads();

    float sum = 0.0f;
#pragma unroll
    for (int p = 0; p < 8; ++p) {
        r[p] = __expf(r[p] - m);
        sum += r[p];
    }
    red[tid] = sum;
    __syncthreads();
#pragma unroll
    for (int s = 128; s > 0; s >>= 1) {
        if (tid < s) red[tid] += red[tid + s];
        __syncthreads();
    }
    const float inv = 1.0f / red[0];

    __half2 h[4];
#pragma unroll
    for (int p = 0; p < 4; ++p)
        h[p] = __floats2half2_rn(r[2 * p] * inv, r[2 * p + 1] * inv);
    *(uint4*)(orow + c0) = *(uint4*)h;
}

__global__ void concat_bias_qk(const float* bq, const float* bk, float* dst)
{
    const int t = blockIdx.x * 256 + threadIdx.x;
    if (t < 512) {
        dst[t] = bq[t];
        dst[512 + t] = bk[t];
    }
}

// ---------------------------------------------------------------------------
// Launch
// ---------------------------------------------------------------------------
extern "C" void kernel_launch(void* const* d_in, const int* in_sizes, int n_in,
                              void* d_out, int out_size)
{
    (void)in_sizes; (void)n_in; (void)out_size;
    const float* h  = (const float*)d_in[1];
    const float* Wv = (const float*)d_in[2];
    const float* bv = (const float*)d_in[3];
    const float* Wk = (const float*)d_in[4];
    const float* bk = (const float*)d_in[5];
    const float* Wq = (const float*)d_in[6];
    const float* bq = (const float*)d_in[7];
    const float* W1 = (const float*)d_in[8];
    const float* b1 = (const float*)d_in[9];
    const float* W2 = (const float*)d_in[10];
    const float* b2 = (const float*)d_in[11];
    float* out = (float*)d_out;

    uint8_t *hs, *qks, *v16, *vt16, *os, *hids, *wqks, *wv16, *w116, *w216;
    float *att, *bqk;
    __half* atth;
    cudaGetSymbolAddress((void**)&hs,   g_h_s);
    cudaGetSymbolAddress((void**)&qks,  g_qk_s);
    cudaGetSymbolAddress((void**)&v16,  g_v16);
    cudaGetSymbolAddress((void**)&vt16, g_vt16);
    cudaGetSymbolAddress((void**)&os,   g_o_s);
    cudaGetSymbolAddress((void**)&hids, g_hid_s);
    cudaGetSymbolAddress((void**)&wqks, g_wqk_s);
    cudaGetSymbolAddress((void**)&wv16, g_wv16);
    cudaGetSymbolAddress((void**)&w116, g_w116);
    cudaGetSymbolAddress((void**)&w216, g_w216);
    cudaGetSymbolAddress((void**)&att,  g_att);
    cudaGetSymbolAddress((void**)&atth, g_atth);
    cudaGetSymbolAddress((void**)&bqk,  g_bqk);

    cudaFuncSetAttribute(hmma_gemm3<true,  1>, cudaFuncAttributeMaxDynamicSharedMemorySize, G3_SMEM);
    cudaFuncSetAttribute(hmma_gemm3<false, 0>, cudaFuncAttributeMaxDynamicSharedMemorySize, G3_SMEM);
    cudaFuncSetAttribute(hmma_gemm2<true, false, 2>, cudaFuncAttributeMaxDynamicSharedMemorySize, G2_SMEM);
    cudaFuncSetAttribute(hmma_gemm2<true, true,  1>, cudaFuncAttributeMaxDynamicSharedMemorySize, G2_SMEM);
    cudaFuncSetAttribute(hmma_gemm2<true, false, 0>, cudaFuncAttributeMaxDynamicSharedMemorySize, G2_SMEM);
    cudaFuncSetAttribute(hmma_av1, cudaFuncAttributeMaxDynamicSharedMemorySize, AV_SMEM);

    // 0) prep
    concat_bias_qk<<<2, 256>>>(bq, bk, bqk);
    {
        dim3 blk(32, 8), grd(16, 16);
        transpose_split_w16<<<grd, blk>>>(Wq, wqks, 0);
        transpose_split_w16<<<grd, blk>>>(Wk, wqks, 512);
        transpose_plain_w16<<<grd, blk>>>(Wv, (__half*)wv16);
        transpose_plain_w16<<<grd, blk>>>(W1, (__half*)w116);
        transpose_plain_w16<<<grd, blk>>>(W2, (__half*)w216);
    }
    split16_rows512<<<(BN_ROWS * 512 / 8) / 256, 256>>>(h, hs);

    // 1) qk-proj: [32768,1024] = h @ wqk^T + bqk -> qk split (ldc 4096B)
    {
        dim3 grd(1024 / 128, BN_ROWS / 128, 1);
        hmma_gemm3<true, 1><<<grd, 256, G3_SMEM>>>(
            hs, wqks, bqk, nullptr, qks, 512, 2048, 2048, 4096, 0, 0, 0);
    }

    // 2) v-proj: [32768,512] = h @ Wv^T + bv -> v plain fp16 (ldc 1024B)
    {
        dim3 grd(512 / 128, BN_ROWS / 128, 1);
        hmma_gemm2<true, false, 2><<<grd, 256, G2_SMEM>>>(
            hs, wv16, bv, nullptr, v16, 512, 2048, 1024, 1024);
    }

    // 3) v^T per batch (plain fp16)
    {
        dim3 blk(32, 8), grd(16, 64, BB);
        vt_transpose16<<<grd, blk>>>((const __half*)v16, (__half*)vt16);
    }

    // 4) logits: att[b] = q @ k^T (fp32 out)
    {
        dim3 grd(NSEQ / 128, NSEQ / 128, BB);
        hmma_gemm3<false, 0><<<grd, 256, G3_SMEM>>>(
            qks, qks + 2048, nullptr, att, nullptr,
            512, 4096, 4096, 8192,
            2048LL * 4096, 2048LL * 4096, 2048LL * 8192);
    }

    // 5) softmax -> att fp16
    softmax_f16_kernel<<<BN_ROWS, 256>>>(att, atth);

    // 6) o[b] = att @ vt^T (1-MMA fp16) -> o split fp16
    {
        dim3 grd(512 / 128, NSEQ / 128, BB);
        hmma_av1<<<grd, 256, AV_SMEM>>>((const uint8_t*)atth, vt16, os);
    }

    // 7) hid = relu(o @ W1^T + b1) -> hid split fp16
    {
        dim3 grd(512 / 128, BN_ROWS / 128, 1);
        hmma_gemm2<true, true, 1><<<grd, 256, G2_SMEM>>>(
            os, w116, b1, nullptr, hids, 512, 2048, 1024, 2048);
    }

    // 8) out = hid @ W2^T + b2 (fp32 out)
    {
        dim3 grd(512 / 128, BN_ROWS / 128, 1);
        hmma_gemm2<true, false, 0><<<grd, 256, G2_SMEM>>>(
            hids, w216, b2, out, nullptr, 512, 2048, 1024, 2048);
    }
}

// round 7
// speedup vs baseline: 2.9591x; 1.0083x over previous
#include <cuda_runtime.h>
#include <cuda_fp16.h>
#include <math.h>
#include <stdint.h>

// Problem dims (fixed)
#define BB 16
#define NSEQ 2048
#define MM 512
#define HH 512
#define BN_ROWS (BB * NSEQ)   // 32768

// ---------------------------------------------------------------------------
// Split layout (fp16): for a logical [R x K] matrix, 4 bytes/elem as groups of
// 32 columns: each 128B group = 32 fp16 "hi" then 32 fp16 "lo".
// byte(r, c) = r*rowBytes + (c>>5)*128 + (c&31)*2   (hi; lo at +64)
// Plain fp16 layout: byte(r, c) = r*rowBytes + c*2.
// ---------------------------------------------------------------------------
__device__ __align__(128) uint8_t g_h_s  [(long long)BN_ROWS * HH * 4];     // h split
__device__ __align__(128) uint8_t g_qk_s [(long long)BN_ROWS * 1024 * 4];   // q|k split
__device__ __align__(128) uint8_t g_v16  [(long long)BN_ROWS * HH * 2];     // v plain
__device__ __align__(128) uint8_t g_vt16 [(long long)BN_ROWS * HH * 2];     // v^T plain
__device__ __align__(128) uint8_t g_o_s  [(long long)BN_ROWS * HH * 4];     // o split
__device__ __align__(128) uint8_t g_hid_s[(long long)BN_ROWS * HH * 4];     // hid split
__device__ __align__(128) uint8_t g_wqk_s[1024LL * 512 * 4];                // Wq^T|Wk^T split
__device__ __align__(128) uint8_t g_wv16 [512LL * 512 * 2];                 // Wv^T plain
__device__ __align__(128) uint8_t g_w116 [512LL * 512 * 2];                 // W1^T plain
__device__ __align__(128) uint8_t g_w216 [512LL * 512 * 2];                 // W2^T plain
__device__ float g_att[(long long)BB * NSEQ * NSEQ];
__device__ __align__(128) __half g_atth[(long long)BB * NSEQ * NSEQ];
__device__ float g_bqk[1024];

// ---------------------------------------------------------------------------
// Helpers
// ---------------------------------------------------------------------------
__device__ __forceinline__ uint32_t smem_u32(const void* p) {
    uint32_t a;
    asm("{ .reg .u64 t; cvta.to.shared.u64 t, %1; cvt.u32.u64 %0, t; }" : "=r"(a) : "l"(p));
    return a;
}
__device__ __forceinline__ void ldsm4(uint32_t* r, uint32_t addr) {
    asm volatile("ldmatrix.sync.aligned.m8n8.x4.shared.b16 {%0,%1,%2,%3}, [%4];"
                 : "=r"(r[0]), "=r"(r[1]), "=r"(r[2]), "=r"(r[3]) : "r"(addr));
}
__device__ __forceinline__ void mma_f16(float* c, const uint32_t* a,
                                        uint32_t b0, uint32_t b1) {
    asm volatile(
        "mma.sync.aligned.m16n8k16.row.col.f32.f16.f16.f32 "
        "{%0,%1,%2,%3}, {%4,%5,%6,%7}, {%8,%9}, {%0,%1,%2,%3};"
        : "+f"(c[0]), "+f"(c[1]), "+f"(c[2]), "+f"(c[3])
        : "r"(a[0]), "r"(a[1]), "r"(a[2]), "r"(a[3]), "r"(b0), "r"(b1));
}
__device__ __forceinline__ void cp16(uint32_t dst, const void* src) {
    asm volatile("cp.async.cg.shared.global [%0], [%1], 16;" :: "r"(dst), "l"(src));
}
__device__ __forceinline__ void cp_commit() {
    asm volatile("cp.async.commit_group;");
}
template <int N> __device__ __forceinline__ void cp_wait() {
    asm volatile("cp.async.wait_group %0;" :: "n"(N));
}
__device__ __forceinline__ void split2h(float x, float y, uint32_t& hi, uint32_t& lo) {
    __half2 h = __floats2half2_rn(x, y);
    __half2 l = __floats2half2_rn(x - __half2float(h.x), y - __half2float(h.y));
    hi = *(uint32_t*)&h;
    lo = *(uint32_t*)&l;
}

// Plain-fp16 smem tile addressing (64B of data per row, 2 rows packed per 128B
// line, 8-chunk XOR swizzle): conflict-free for ldmatrix and cp.async.
__device__ __forceinline__ uint32_t plainb_addr(uint32_t base, int r, int c) {
    return base + ((r >> 1) << 7) + (((((r & 1) << 2) + c) ^ ((r >> 1) & 7)) << 4);
}

// OUTMODE: 0 = fp32, 1 = split fp16, 2 = plain fp16
#define STAGES 3

// ---------------------------------------------------------------------------
// gemm3: A split fp16, B split fp16, 3 MMAs (HH, HL, LH).
// C[M,N] = A[M,K] @ B[N,K]^T (+bias). CTA 128x128, K staged 32, 3-deep cp.async.
// ---------------------------------------------------------------------------
#define G3_STAGE 32768
#define G3_SMEM (STAGES * G3_STAGE)

template <bool HAS_BIAS, int OUTMODE>
__global__ __launch_bounds__(256, 2)
void hmma_gemm3(const uint8_t* __restrict__ A, const uint8_t* __restrict__ B,
                const float* __restrict__ bias, float* __restrict__ Cf,
                uint8_t* __restrict__ Cs,
                int K, long long ldaB, long long ldbB, long long ldcB,
                long long sA, long long sB, long long sC)
{
    extern __shared__ uint8_t sm[];
    const long long bz = blockIdx.z;
    A += bz * sA;
    B += bz * sB;

    const int tid = threadIdx.x;
    const int wid = tid >> 5, lane = tid & 31;
    const int wm = wid & 3, wn = wid >> 2;
    const int lr = lane & 15, lc = lane >> 4;
    const int m0 = blockIdx.y * 128, n0 = blockIdx.x * 128;

    const int lrow = tid >> 1;
    const int cb = (tid & 1) * 4;
    const int rsw = lrow & 7;

    const uint32_t smb = smem_u32(sm);
    const uint8_t* srcA0 = A + (long long)(m0 + lrow) * ldaB + cb * 16;
    const uint8_t* srcB0 = B + (long long)(n0 + lrow) * ldbB + cb * 16;

    float acc[2][8][4];
#pragma unroll
    for (int i = 0; i < 2; ++i)
#pragma unroll
        for (int j = 0; j < 8; ++j)
#pragma unroll
            for (int t = 0; t < 4; ++t) acc[i][j][t] = 0.0f;

    const int S = K / 32;

#define G3_ISSUE(s)                                                           \
    do {                                                                      \
        const uint32_t dra = smb + ((s) % STAGES) * G3_STAGE + lrow * 128;    \
        const uint8_t* pa = srcA0 + (s) * 128;                                \
        const uint8_t* pb = srcB0 + (s) * 128;                                \
        _Pragma("unroll")                                                     \
        for (int c = 0; c < 4; ++c)                                           \
            cp16(dra + (((cb + c) ^ rsw) << 4), pa + c * 16);                 \
        _Pragma("unroll")                                                     \
        for (int c = 0; c < 4; ++c)                                           \
            cp16(dra + 16384 + (((cb + c) ^ rsw) << 4), pb + c * 16);         \
        cp_commit();                                                          \
    } while (0)

    G3_ISSUE(0);
    G3_ISSUE(1);

    for (int s = 0; s < S; ++s) {
        if (s + 1 < S) cp_wait<1>(); else cp_wait<0>();
        __syncthreads();
        if (s + 2 < S) G3_ISSUE(s + 2);

        const uint32_t bufA = smb + (s % STAGES) * G3_STAGE;
        const uint32_t bufB = bufA + 16384;

#pragma unroll
        for (int kk = 0; kk < 2; ++kk) {
            uint32_t aH[2][4], aL[2][4];
#pragma unroll
            for (int mi = 0; mi < 2; ++mi) {
                const int r = wm * 32 + mi * 16 + lr;
                const int byteh = kk * 32 + lc * 16;
                const uint32_t rb = bufA + r * 128;
                const int rs = r & 7;
                ldsm4(aH[mi], rb + ((((byteh) >> 4) ^ rs) << 4));
                ldsm4(aL[mi], rb + ((((byteh + 64) >> 4) ^ rs) << 4));
            }
#pragma unroll
            for (int g = 0; g < 4; ++g) {
                const int r = wn * 64 + g * 16 + lr;
                const int byteh = kk * 32 + lc * 16;
                const uint32_t rb = bufB + r * 128;
                const int rs = r & 7;
                uint32_t bh[4], bl[4];
                ldsm4(bh, rb + ((((byteh) >> 4) ^ rs) << 4));
                ldsm4(bl, rb + ((((byteh + 64) >> 4) ^ rs) << 4));
#pragma unroll
                for (int mi = 0; mi < 2; ++mi) {
                    mma_f16(acc[mi][2 * g],     aH[mi], bh[0], bh[2]);
                    mma_f16(acc[mi][2 * g],     aH[mi], bl[0], bl[2]);
                    mma_f16(acc[mi][2 * g],     aL[mi], bh[0], bh[2]);
                    mma_f16(acc[mi][2 * g + 1], aH[mi], bh[1], bh[3]);
                    mma_f16(acc[mi][2 * g + 1], aH[mi], bl[1], bl[3]);
                    mma_f16(acc[mi][2 * g + 1], aL[mi], bh[1], bh[3]);
                }
            }
        }
    }
#undef G3_ISSUE

#pragma unroll
    for (int mi = 0; mi < 2; ++mi) {
        const long long r0 = m0 + wm * 32 + mi * 16 + (lane >> 2);
#pragma unroll
        for (int nj = 0; nj < 8; ++nj) {
            const int col = n0 + wn * 64 + nj * 8 + 2 * (lane & 3);
            float bx = 0.0f, by = 0.0f;
            if (HAS_BIAS) {
                const float2 bvv = *(const float2*)(bias + col);
                bx = bvv.x; by = bvv.y;
            }
            const float x0 = acc[mi][nj][0] + bx;
            const float x1 = acc[mi][nj][1] + by;
            const float x2 = acc[mi][nj][2] + bx;
            const float x3 = acc[mi][nj][3] + by;
            if (OUTMODE == 0) {
                uint8_t* base = (uint8_t*)Cf + bz * sC;
                *(float2*)(base + r0 * ldcB + col * 4)       = make_float2(x0, x1);
                *(float2*)(base + (r0 + 8) * ldcB + col * 4) = make_float2(x2, x3);
            } else {
                uint8_t* base = Cs + bz * sC;
                const long long cb0 = (long long)(col >> 5) * 128 + (col & 31) * 2;
                uint32_t hi, lo;
                split2h(x0, x1, hi, lo);
                uint8_t* p = base + r0 * ldcB + cb0;
                *(uint32_t*)p = hi;
                *(uint32_t*)(p + 64) = lo;
                split2h(x2, x3, hi, lo);
                p = base + (r0 + 8) * ldcB + cb0;
                *(uint32_t*)p = hi;
                *(uint32_t*)(p + 64) = lo;
            }
        }
    }
}

// ---------------------------------------------------------------------------
// gemm2: A split fp16, B plain fp16 (single), 2 MMAs (aH*b + aL*b).
// ---------------------------------------------------------------------------
#define G2_STAGE 24576
#define G2_SMEM (STAGES * G2_STAGE)

template <bool HAS_BIAS, bool RELU, int OUTMODE>
__global__ __launch_bounds__(256, 2)
void hmma_gemm2(const uint8_t* __restrict__ A, const uint8_t* __restrict__ B,
                const float* __restrict__ bias, float* __restrict__ Cf,
                uint8_t* __restrict__ Cs,
                int K, long long ldaB, long long ldbB, long long ldcB)
{
    extern __shared__ uint8_t sm[];
    const int tid = threadIdx.x;
    const int wid = tid >> 5, lane = tid & 31;
    const int wm = wid & 3, wn = wid >> 2;
    const int lr = lane & 15, lc = lane >> 4;
    const int m0 = blockIdx.y * 128, n0 = blockIdx.x * 128;

    const int lrow = tid >> 1;
    const int cbA = (tid & 1) * 4;
    const int cbB = (tid & 1) * 2;
    const int rsw = lrow & 7;

    const uint32_t smb = smem_u32(sm);
    const uint8_t* srcA0 = A + (long long)(m0 + lrow) * ldaB + cbA * 16;
    const uint8_t* srcB0 = B + (long long)(n0 + lrow) * ldbB + cbB * 16;

    float acc[2][8][4];
#pragma unroll
    for (int i = 0; i < 2; ++i)
#pragma unroll
        for (int j = 0; j < 8; ++j)
#pragma unroll
            for (int t = 0; t < 4; ++t) acc[i][j][t] = 0.0f;

    const int S = K / 32;

#define G2_ISSUE(s)                                                           \
    do {                                                                      \
        const uint32_t stb = smb + ((s) % STAGES) * G2_STAGE;                 \
        const uint8_t* pa = srcA0 + (s) * 128;                                \
        const uint8_t* pb = srcB0 + (s) * 64;                                 \
        const uint32_t dra = stb + lrow * 128;                                \
        _Pragma("unroll")                                                     \
        for (int c = 0; c < 4; ++c)                                           \
            cp16(dra + (((cbA + c) ^ rsw) << 4), pa + c * 16);                \
        _Pragma("unroll")                                                     \
        for (int c = 0; c < 2; ++c)                                           \
            cp16(plainb_addr(stb + 16384, lrow, cbB + c), pb + c * 16);       \
        cp_commit();                                                          \
    } while (0)

    G2_ISSUE(0);
    G2_ISSUE(1);

    for (int s = 0; s < S; ++s) {
        if (s + 1 < S) cp_wait<1>(); else cp_wait<0>();
        __syncthreads();
        if (s + 2 < S) G2_ISSUE(s + 2);

        const uint32_t bufA = smb + (s % STAGES) * G2_STAGE;
        const uint32_t bufB = bufA + 16384;

#pragma unroll
        for (int kk = 0; kk < 2; ++kk) {
            uint32_t aH[2][4], aL[2][4];
#pragma unroll
            for (int mi = 0; mi < 2; ++mi) {
                const int r = wm * 32 + mi * 16 + lr;
                const int byteh = kk * 32 + lc * 16;
                const uint32_t rb = bufA + r * 128;
                const int rs = r & 7;
                ldsm4(aH[mi], rb + ((((byteh) >> 4) ^ rs) << 4));
                ldsm4(aL[mi], rb + ((((byteh + 64) >> 4) ^ rs) << 4));
            }
#pragma unroll
            for (int g = 0; g < 4; ++g) {
                const int r = wn * 64 + g * 16 + lr;
                const int c = kk * 2 + lc;
                uint32_t b[4];
                ldsm4(b, plainb_addr(bufB, r, c));
#pragma unroll
                for (int mi = 0; mi < 2; ++mi) {
                    mma_f16(acc[mi][2 * g],     aH[mi], b[0], b[2]);
                    mma_f16(acc[mi][2 * g],     aL[mi], b[0], b[2]);
                    mma_f16(acc[mi][2 * g + 1], aH[mi], b[1], b[3]);
                    mma_f16(acc[mi][2 * g + 1], aL[mi], b[1], b[3]);
                }
            }
        }
    }
#undef G2_ISSUE

#pragma unroll
    for (int mi = 0; mi < 2; ++mi) {
        const long long r0 = m0 + wm * 32 + mi * 16 + (lane >> 2);
#pragma unroll
        for (int nj = 0; nj < 8; ++nj) {
            const int col = n0 + wn * 64 + nj * 8 + 2 * (lane & 3);
            float bx = 0.0f, by = 0.0f;
            if (HAS_BIAS) {
                const float2 bvv = *(const float2*)(bias + col);
                bx = bvv.x; by = bvv.y;
            }
            float x0 = acc[mi][nj][0] + bx;
            float x1 = acc[mi][nj][1] + by;
            float x2 = acc[mi][nj][2] + bx;
            float x3 = acc[mi][nj][3] + by;
            if (RELU) {
                x0 = fmaxf(x0, 0.0f); x1 = fmaxf(x1, 0.0f);
                x2 = fmaxf(x2, 0.0f); x3 = fmaxf(x3, 0.0f);
            }
            if (OUTMODE == 0) {
                *(float2*)((uint8_t*)Cf + r0 * ldcB + col * 4)       = make_float2(x0, x1);
                *(float2*)((uint8_t*)Cf + (r0 + 8) * ldcB + col * 4) = make_float2(x2, x3);
            } else if (OUTMODE == 1) {
                const long long cb0 = (long long)(col >> 5) * 128 + (col & 31) * 2;
                uint32_t hi, lo;
                split2h(x0, x1, hi, lo);
                uint8_t* p = Cs + r0 * ldcB + cb0;
                *(uint32_t*)p = hi;
                *(uint32_t*)(p + 64) = lo;
                split2h(x2, x3, hi, lo);
                p = Cs + (r0 + 8) * ldcB + cb0;
                *(uint32_t*)p = hi;
                *(uint32_t*)(p + 64) = lo;
            } else {
                __half2 v01 = __floats2half2_rn(x0, x1);
                __half2 v23 = __floats2half2_rn(x2, x3);
                *(uint32_t*)(Cs + r0 * ldcB + col * 2)       = *(uint32_t*)&v01;
                *(uint32_t*)(Cs + (r0 + 8) * ldcB + col * 2) = *(uint32_t*)&v23;
            }
        }
    }
}

// ---------------------------------------------------------------------------
// av1: o[b] = att[b] @ vt[b]^T; both plain fp16, 1 MMA. Out: o split fp16.
// ---------------------------------------------------------------------------
#define AV_STAGE 16384
#define AV_SMEM (STAGES * AV_STAGE)

__global__ __launch_bounds__(256, 2)
void hmma_av1(const uint8_t* __restrict__ A, const uint8_t* __restrict__ B,
              uint8_t* __restrict__ Cs)
{
    extern __shared__ uint8_t sm[];
    const long long bz = blockIdx.z;
    A += bz * (long long)NSEQ * 4096;       // att rows, 2048 fp16
    B += bz * 512LL * 4096;                 // vt rows, 2048 fp16

    const int tid = threadIdx.x;
    const int wid = tid >> 5, lane = tid & 31;
    const int wm = wid & 3, wn = wid >> 2;
    const int lr = lane & 15, lc = lane >> 4;
    const int m0 = blockIdx.y * 128, n0 = blockIdx.x * 128;

    const int lrow = tid >> 1;
    const int cb2 = (tid & 1) * 2;

    const uint32_t smb = smem_u32(sm);
    const uint8_t* srcA0 = A + (long long)(m0 + lrow) * 4096 + cb2 * 16;
    const uint8_t* srcB0 = B + (long long)(n0 + lrow) * 4096 + cb2 * 16;

    float acc[2][8][4];
#pragma unroll
    for (int i = 0; i < 2; ++i)
#pragma unroll
        for (int j = 0; j < 8; ++j)
#pragma unroll
            for (int t = 0; t < 4; ++t) acc[i][j][t] = 0.0f;

    const int S = NSEQ / 32;  // 64

#define AV_ISSUE(s)                                                           \
    do {                                                                      \
        const uint32_t stb = smb + ((s) % STAGES) * AV_STAGE;                 \
        const uint8_t* pa = srcA0 + (s) * 64;                                 \
        const uint8_t* pb = srcB0 + (s) * 64;                                 \
        _Pragma("unroll")                                                     \
        for (int c = 0; c < 2; ++c)                                           \
            cp16(plainb_addr(stb, lrow, cb2 + c), pa + c * 16);               \
        _Pragma("unroll")                                                     \
        for (int c = 0; c < 2; ++c)                                           \
            cp16(plainb_addr(stb + 8192, lrow, cb2 + c), pb + c * 16);        \
        cp_commit();                                                          \
    } while (0)

    AV_ISSUE(0);
    AV_ISSUE(1);

    for (int s = 0; s < S; ++s) {
        if (s + 1 < S) cp_wait<1>(); else cp_wait<0>();
        __syncthreads();
        if (s + 2 < S) AV_ISSUE(s + 2);

        const uint32_t bufA = smb + (s % STAGES) * AV_STAGE;
        const uint32_t bufB = bufA + 8192;

#pragma unroll
        for (int kk = 0; kk < 2; ++kk) {
            const int c = kk * 2 + lc;
            uint32_t aF[2][4];
#pragma unroll
            for (int mi = 0; mi < 2; ++mi) {
                const int r = wm * 32 + mi * 16 + lr;
                ldsm4(aF[mi], plainb_addr(bufA, r, c));
            }
#pragma unroll
            for (int g = 0; g < 4; ++g) {
                const int r = wn * 64 + g * 16 + lr;
                uint32_t b[4];
                ldsm4(b, plainb_addr(bufB, r, c));
#pragma unroll
                for (int mi = 0; mi < 2; ++mi) {
                    mma_f16(acc[mi][2 * g],     aF[mi], b[0], b[2]);
                    mma_f16(acc[mi][2 * g + 1], aF[mi], b[1], b[3]);
                }
            }
        }
    }
#undef AV_ISSUE

    // epilogue: o split fp16, global rows
#pragma unroll
    for (int mi = 0; mi < 2; ++mi) {
        const long long r0 = bz * NSEQ + m0 + wm * 32 + mi * 16 + (lane >> 2);
#pragma unroll
        for (int nj = 0; nj < 8; ++nj) {
            const int col = n0 + wn * 64 + nj * 8 + 2 * (lane & 3);
            const long long cb0 = (long long)(col >> 5) * 128 + (col & 31) * 2;
            uint32_t hi, lo;
            split2h(acc[mi][nj][0], acc[mi][nj][1], hi, lo);
            uint8_t* p = Cs + r0 * 2048 + cb0;
            *(uint32_t*)p = hi;
            *(uint32_t*)(p + 64) = lo;
            split2h(acc[mi][nj][2], acc[mi][nj][3], hi, lo);
            p = Cs + (r0 + 8) * 2048 + cb0;
            *(uint32_t*)p = hi;
            *(uint32_t*)(p + 64) = lo;
        }
    }
}

// ---------------------------------------------------------------------------
// Prep kernels
// ---------------------------------------------------------------------------
__global__ __launch_bounds__(256)
void split16_rows512(const float* __restrict__ in, uint8_t* __restrict__ out)
{
    const long long i8 = ((long long)blockIdx.x * 256 + threadIdx.x) * 8;
    const long long row = i8 >> 9;
    const int col = (int)(i8 & 511);
    const float4 a = *(const float4*)(in + i8);
    const float4 b = *(const float4*)(in + i8 + 4);
    uint4 hi, lo;
    split2h(a.x, a.y, hi.x, lo.x);
    split2h(a.z, a.w, hi.y, lo.y);
    split2h(b.x, b.y, hi.z, lo.z);
    split2h(b.z, b.w, hi.w, lo.w);
    uint8_t* p = out + row * 2048 + (col >> 5) * 128 + (col & 31) * 2;
    *(uint4*)p = hi;
    *(uint4*)(p + 64) = lo;
}

__global__ __launch_bounds__(256)
void transpose_split_w16(const float* __restrict__ in, uint8_t* __restrict__ out,
                         long long rowOff)
{
    __shared__ float t[32][33];
    const int c0 = blockIdx.x * 32;
    const int r0 = blockIdx.y * 32;
    const int x = threadIdx.x;
    const int y = threadIdx.y;
#pragma unroll
    for (int j = 0; j < 32; j += 8)
        t[y + j][x] = in[(long long)(r0 + y + j) * 512 + c0 + x];
    __syncthreads();
#pragma unroll
    for (int j = 0; j < 32; j += 8) {
        const float val = t[x][y + j];
        const long long row = rowOff + c0 + y + j;
        const int col = r0 + x;
        __half hi = __float2half_rn(val);
        __half lo = __float2half_rn(val - __half2float(hi));
        uint8_t* p = out + row * 2048 + (col >> 5) * 128 + (col & 31) * 2;
        *(__half*)p = hi;
        *(__half*)(p + 64) = lo;
    }
}

__global__ __launch_bounds__(256)
void transpose_plain_w16(const float* __restrict__ in, __half* __restrict__ out)
{
    __shared__ float t[32][33];
    const int c0 = blockIdx.x * 32;
    const int r0 = blockIdx.y * 32;
    const int x = threadIdx.x;
    const int y = threadIdx.y;
#pragma unroll
    for (int j = 0; j < 32; j += 8)
        t[y + j][x] = in[(long long)(r0 + y + j) * 512 + c0 + x];
    __syncthreads();
#pragma unroll
    for (int j = 0; j < 32; j += 8)
        out[(long long)(c0 + y + j) * 512 + r0 + x] = __float2half_rn(t[x][y + j]);
}

__global__ __launch_bounds__(256)
void vt_transpose16(const __half* __restrict__ v, __half* __restrict__ vt)
{
    __shared__ __half t[32][33];
    const long long b = blockIdx.z;
    const int h0 = blockIdx.x * 32;
    const int n0 = blockIdx.y * 32;
    const int x = threadIdx.x;
    const int y = threadIdx.y;
#pragma unroll
    for (int j = 0; j < 32; j += 8)
        t[y + j][x] = v[(b * 2048 + n0 + y + j) * 512 + h0 + x];
    __syncthreads();
#pragma unroll
    for (int j = 0; j < 32; j += 8)
        vt[b * 512 * 2048 + (long long)(h0 + y + j) * 2048 + n0 + x] = t[x][y + j];
}

// ---------------------------------------------------------------------------
// Row softmax (2048) fp32 -> fp16, with threshold-gated exp.
// Logits ~ N(0, 512); values more than 25 below the row max produce
// exp < 1.4e-11, below fp16's smallest subnormal -> output is exactly 0
// either way, and the sum contribution (< 3e-8 relative) is negligible.
// ~98.6% of 8-element thread chunks skip the MUFU exp entirely.
// ---------------------------------------------------------------------------
__global__ __launch_bounds__(256)
void softmax_f16_kernel(const float* __restrict__ att, __half* __restrict__ outh)
{
    const float* row = att + (long long)blockIdx.x * NSEQ;
    __half* orow = outh + (long long)blockIdx.x * NSEQ;
    __shared__ float sred[8];
    const int tid = threadIdx.x;
    const int wid = tid >> 5;
    const int lane = tid & 31;
    const int c0 = tid * 8;

    float r[8];
    *(float4*)&r[0] = *(const float4*)(row + c0);
    *(float4*)&r[4] = *(const float4*)(row + c0 + 4);

    // local max (kept), then warp+block max
    float lmax = r[0];
#pragma unroll
    for (int p = 1; p < 8; ++p) lmax = fmaxf(lmax, r[p]);
    float m = lmax;
#pragma unroll
    for (int off = 16; off > 0; off >>= 1)
        m = fmaxf(m, __shfl_xor_sync(0xFFFFFFFFu, m, off));
    if (lane == 0) sred[wid] = m;
    __syncthreads();
    float M = sred[0];
#pragma unroll
    for (int w = 1; w < 8; ++w) M = fmaxf(M, sred[w]);

    // gated exp
    float sum = 0.0f;
    if (lmax - M > -25.0f) {
#pragma unroll
        for (int p = 0; p < 8; ++p) {
            r[p] = __expf(r[p] - M);
            sum += r[p];
        }
    } else {
#pragma unroll
        for (int p = 0; p < 8; ++p) r[p] = 0.0f;
    }

    // warp+block sum
#pragma unroll
    for (int off = 16; off > 0; off >>= 1)
        sum += __shfl_xor_sync(0xFFFFFFFFu, sum, off);
    __syncthreads();           // protect sred reuse
    if (lane == 0) sred[wid] = sum;
    __syncthreads();
    float S = sred[0];
#pragma unroll
    for (int w = 1; w < 8; ++w) S += sred[w];
    const float inv = 1.0f / S;

    __half2 hh[4];
#pragma unroll
    for (int p = 0; p < 4; ++p)
        hh[p] = __floats2half2_rn(r[2 * p] * inv, r[2 * p + 1] * inv);
    *(uint4*)(orow + c0) = *(uint4*)hh;
}

__global__ void concat_bias_qk(const float* bq, const float* bk, float* dst)
{
    const int t = blockIdx.x * 256 + threadIdx.x;
    if (t < 512) {
        dst[t] = bq[t];
        dst[512 + t] = bk[t];
    }
}

// ---------------------------------------------------------------------------
// Launch
// ---------------------------------------------------------------------------
extern "C" void kernel_launch(void* const* d_in, const int* in_sizes, int n_in,
                              void* d_out, int out_size)
{
    (void)in_sizes; (void)n_in; (void)out_size;
    const float* h  = (const float*)d_in[1];
    const float* Wv = (const float*)d_in[2];
    const float* bv = (const float*)d_in[3];
    const float* Wk = (const float*)d_in[4];
    const float* bk = (const float*)d_in[5];
    const float* Wq = (const float*)d_in[6];
    const float* bq = (const float*)d_in[7];
    const float* W1 = (const float*)d_in[8];
    const float* b1 = (const float*)d_in[9];
    const float* W2 = (const float*)d_in[10];
    const float* b2 = (const float*)d_in[11];
    float* out = (float*)d_out;

    uint8_t *hs, *qks, *v16, *vt16, *os, *hids, *wqks, *wv16, *w116, *w216;
    float *att, *bqk;
    __half* atth;
    cudaGetSymbolAddress((void**)&hs,   g_h_s);
    cudaGetSymbolAddress((void**)&qks,  g_qk_s);
    cudaGetSymbolAddress((void**)&v16,  g_v16);
    cudaGetSymbolAddress((void**)&vt16, g_vt16);
    cudaGetSymbolAddress((void**)&os,   g_o_s);
    cudaGetSymbolAddress((void**)&hids, g_hid_s);
    cudaGetSymbolAddress((void**)&wqks, g_wqk_s);
    cudaGetSymbolAddress((void**)&wv16, g_wv16);
    cudaGetSymbolAddress((void**)&w116, g_w116);
    cudaGetSymbolAddress((void**)&w216, g_w216);
    cudaGetSymbolAddress((void**)&att,  g_att);
    cudaGetSymbolAddress((void**)&atth, g_atth);
    cudaGetSymbolAddress((void**)&bqk,  g_bqk);

    cudaFuncSetAttribute(hmma_gemm3<true,  1>, cudaFuncAttributeMaxDynamicSharedMemorySize, G3_SMEM);
    cudaFuncSetAttribute(hmma_gemm3<false, 0>, cudaFuncAttributeMaxDynamicSharedMemorySize, G3_SMEM);
    cudaFuncSetAttribute(hmma_gemm2<true, false, 2>, cudaFuncAttributeMaxDynamicSharedMemorySize, G2_SMEM);
    cudaFuncSetAttribute(hmma_gemm2<true, true,  1>, cudaFuncAttributeMaxDynamicSharedMemorySize, G2_SMEM);
    cudaFuncSetAttribute(hmma_gemm2<true, false, 0>, cudaFuncAttributeMaxDynamicSharedMemorySize, G2_SMEM);
    cudaFuncSetAttribute(hmma_av1, cudaFuncAttributeMaxDynamicSharedMemorySize, AV_SMEM);

    // 0) prep
    concat_bias_qk<<<2, 256>>>(bq, bk, bqk);
    {
        dim3 blk(32, 8), grd(16, 16);
        transpose_split_w16<<<grd, blk>>>(Wq, wqks, 0);
        transpose_split_w16<<<grd, blk>>>(Wk, wqks, 512);
        transpose_plain_w16<<<grd, blk>>>(Wv, (__half*)wv16);
        transpose_plain_w16<<<grd, blk>>>(W1, (__half*)w116);
        transpose_plain_w16<<<grd, blk>>>(W2, (__half*)w216);
    }
    split16_rows512<<<(BN_ROWS * 512 / 8) / 256, 256>>>(h, hs);

    // 1) qk-proj: [32768,1024] = h @ wqk^T + bqk -> qk split (ldc 4096B)
    {
        dim3 grd(1024 / 128, BN_ROWS / 128, 1);
        hmma_gemm3<true, 1><<<grd, 256, G3_SMEM>>>(
            hs, wqks, bqk, nullptr, qks, 512, 2048, 2048, 4096, 0, 0, 0);
    }

    // 2) v-proj: [32768,512] = h @ Wv^T + bv -> v plain fp16 (ldc 1024B)
    {
        dim3 grd(512 / 128, BN_ROWS / 128, 1);
        hmma_gemm2<true, false, 2><<<grd, 256, G2_SMEM>>>(
            hs, wv16, bv, nullptr, v16, 512, 2048, 1024, 1024);
    }

    // 3) v^T per batch (plain fp16)
    {
        dim3 blk(32, 8), grd(16, 64, BB);
        vt_transpose16<<<grd, blk>>>((const __half*)v16, (__half*)vt16);
    }

    // 4) logits: att[b] = q @ k^T (fp32 out)
    {
        dim3 grd(NSEQ / 128, NSEQ / 128, BB);
        hmma_gemm3<false, 0><<<grd, 256, G3_SMEM>>>(
            qks, qks + 2048, nullptr, att, nullptr,
            512, 4096, 4096, 8192,
            2048LL * 4096, 2048LL * 4096, 2048LL * 8192);
    }

    // 5) softmax -> att fp16 (threshold-gated exp)
    softmax_f16_kernel<<<BN_ROWS, 256>>>(att, atth);

    // 6) o[b] = att @ vt^T (1-MMA fp16) -> o split fp16
    {
        dim3 grd(512 / 128, NSEQ / 128, BB);
        hmma_av1<<<grd, 256, AV_SMEM>>>((const uint8_t*)atth, vt16, os);
    }

    // 7) hid = relu(o @ W1^T + b1) -> hid split fp16
    {
        dim3 grd(512 / 128, BN_ROWS / 128, 1);
        hmma_gemm2<true, true, 1><<<grd, 256, G2_SMEM>>>(
            os, w116, b1, nullptr, hids, 512, 2048, 1024, 2048);
    }

    // 8) out = hid @ W2^T + b2 (fp32 out)
    {
        dim3 grd(512 / 128, BN_ROWS / 128, 1);
        hmma_gemm2<true, false, 0><<<grd, 256, G2_SMEM>>>(
            hids, w216, b2, out, nullptr, 512, 2048, 1024, 2048);
    }
}